// round 2
// baseline (speedup 1.0000x reference)
#include <cuda_runtime.h>
#include <math.h>

#define NB 1576
#define NT 30
#define ND 1024
#define NH 128
#define NM (NB*NT)   // 47280

// scratch for intermediate h [B,T,H]
__device__ float g_h[(size_t)NM * NH];

// ---------------------------------------------------------------------------
// Kernel A: h = LayerNorm(x @ W1 + b1)   [47280,1024]@[1024,128]
// Tile: 48 rows x 128 cols per block, 256 threads, 6x4 outputs/thread.
// ---------------------------------------------------------------------------
__global__ __launch_bounds__(256) void k_gemm1_ln(
    const float* __restrict__ x, const float* __restrict__ W1,
    const float* __restrict__ b1, const float* __restrict__ ln_g,
    const float* __restrict__ ln_b)
{
    __shared__ float xs[48][32];
    __shared__ float ws[32][128];
    int tid = threadIdx.x;
    int cg = tid & 31;     // cols 4*cg .. 4*cg+3
    int rg = tid >> 5;     // rows rg*6 .. rg*6+5 (warp == row group)
    int row0 = blockIdx.x * 48;

    float acc[6][4];
#pragma unroll
    for (int i = 0; i < 6; i++) { acc[i][0]=0.f; acc[i][1]=0.f; acc[i][2]=0.f; acc[i][3]=0.f; }

    for (int k0 = 0; k0 < ND; k0 += 32) {
        // load x tile 48x32
        for (int idx = tid; idx < 48*8; idx += 256) {
            int r = idx >> 3, j = idx & 7;
            *(float4*)&xs[r][4*j] = *(const float4*)(x + (size_t)(row0 + r)*ND + k0 + 4*j);
        }
        // load W1 tile 32x128
        for (int idx = tid; idx < 32*32; idx += 256) {
            int kk = idx >> 5, jc = idx & 31;
            *(float4*)&ws[kk][4*jc] = *(const float4*)(W1 + (size_t)(k0+kk)*NH + 4*jc);
        }
        __syncthreads();
#pragma unroll 8
        for (int kk = 0; kk < 32; kk++) {
            float4 wv = *(const float4*)&ws[kk][4*cg];
#pragma unroll
            for (int i = 0; i < 6; i++) {
                float xv = xs[rg*6+i][kk];
                acc[i][0] += xv*wv.x; acc[i][1] += xv*wv.y;
                acc[i][2] += xv*wv.z; acc[i][3] += xv*wv.w;
            }
        }
        __syncthreads();
    }

    float4 bv = *(const float4*)(b1 + 4*cg);
    float4 gv = *(const float4*)(ln_g + 4*cg);
    float4 bt = *(const float4*)(ln_b + 4*cg);

#pragma unroll
    for (int i = 0; i < 6; i++) {
        float v0 = acc[i][0] + bv.x, v1 = acc[i][1] + bv.y;
        float v2 = acc[i][2] + bv.z, v3 = acc[i][3] + bv.w;
        float s  = v0+v1+v2+v3;
        float ss = v0*v0+v1*v1+v2*v2+v3*v3;
#pragma unroll
        for (int o = 16; o; o >>= 1) {
            s  += __shfl_xor_sync(0xffffffffu, s,  o);
            ss += __shfl_xor_sync(0xffffffffu, ss, o);
        }
        float mean = s * (1.f/128.f);
        float var  = ss * (1.f/128.f) - mean*mean;
        float rstd = rsqrtf(var + 1e-5f);
        float4 o4;
        o4.x = (v0-mean)*rstd*gv.x + bt.x;
        o4.y = (v1-mean)*rstd*gv.y + bt.y;
        o4.z = (v2-mean)*rstd*gv.z + bt.z;
        o4.w = (v3-mean)*rstd*gv.w + bt.w;
        int row = row0 + rg*6 + i;
        *(float4*)(g_h + (size_t)row*NH + 4*cg) = o4;
    }
}

// ---------------------------------------------------------------------------
// Kernel B: per-batch FRU gate + LN + single-head attention, fully in SMEM.
// One block per batch (1576 blocks), 256 threads, ~100 KB dynamic smem.
// ---------------------------------------------------------------------------
struct SmemC {
    float h [32][128];
    float hn[32][128];   // later reused for attention output o
    float q [32][128];
    float k [32][128];
    float v [32][128];
    float wbuf[32][128];
    float sc[30][32];
    float gate[32];
    float rowm[32];
};

__device__ __forceinline__ void small_gemm_qkv(
    SmemC* s, const float* __restrict__ W, const float* __restrict__ bias,
    float (*out)[128], int cg, int rg, const int* rws, const bool* rv, int tid)
{
    float acc[4][4];
#pragma unroll
    for (int i = 0; i < 4; i++) { acc[i][0]=0.f; acc[i][1]=0.f; acc[i][2]=0.f; acc[i][3]=0.f; }
    for (int kc = 0; kc < 4; kc++) {
        for (int idx = tid; idx < 1024; idx += 256) {
            int kk = idx >> 5, jc = idx & 31;
            *(float4*)&s->wbuf[kk][4*jc] = *(const float4*)(W + (size_t)(kc*32+kk)*NH + 4*jc);
        }
        __syncthreads();
#pragma unroll 8
        for (int kk = 0; kk < 32; kk++) {
            float4 wv = *(const float4*)&s->wbuf[kk][4*cg];
#pragma unroll
            for (int i = 0; i < 4; i++) {
                float xv = s->hn[rws[i]][kc*32+kk];
                acc[i][0] += xv*wv.x; acc[i][1] += xv*wv.y;
                acc[i][2] += xv*wv.z; acc[i][3] += xv*wv.w;
            }
        }
        __syncthreads();
    }
    float4 bb = *(const float4*)(bias + 4*cg);
#pragma unroll
    for (int i = 0; i < 4; i++) {
        if (rv[i]) {
            float4 o4;
            o4.x = acc[i][0]+bb.x; o4.y = acc[i][1]+bb.y;
            o4.z = acc[i][2]+bb.z; o4.w = acc[i][3]+bb.w;
            *(float4*)&out[rws[i]][4*cg] = o4;
        }
    }
}

__global__ __launch_bounds__(256) void k_attn(
    const float* __restrict__ T_W, const float* __restrict__ T_b,
    const float* __restrict__ Wq, const float* __restrict__ bq,
    const float* __restrict__ Wk, const float* __restrict__ bk,
    const float* __restrict__ Wv, const float* __restrict__ bv,
    const float* __restrict__ Wo, const float* __restrict__ bo,
    const float* __restrict__ n_g, const float* __restrict__ n_b)
{
    extern __shared__ char smem_raw[];
    SmemC* s = (SmemC*)smem_raw;
    int tid = threadIdx.x;
    int lane = tid & 31, wid = tid >> 5;
    int b = blockIdx.x;
    float* hg = g_h + (size_t)b * NT * NH;

    // load h (30x128)
    for (int idx = tid; idx < NT*NH/4; idx += 256)
        ((float4*)&s->h[0][0])[idx] = ((const float4*)hg)[idx];
    __syncthreads();

    // row means over channels
    for (int r = wid; r < NT; r += 8) {
        float a = s->h[r][lane] + s->h[r][lane+32] + s->h[r][lane+64] + s->h[r][lane+96];
#pragma unroll
        for (int o = 16; o; o >>= 1) a += __shfl_xor_sync(0xffffffffu, a, o);
        if (lane == 0) s->rowm[r] = a * (1.f/128.f);
    }
    __syncthreads();

    // gate: g = softmax(rowm @ T_W + T_b) over time
    if (wid == 0) {
        float val = -1e30f;
        if (lane < NT) {
            float a = T_b[lane];
            for (int u = 0; u < NT; u++) a += s->rowm[u] * T_W[u*NT + lane];
            val = a;
        }
        float m = val;
#pragma unroll
        for (int o = 16; o; o >>= 1) m = fmaxf(m, __shfl_xor_sync(0xffffffffu, m, o));
        float e = (lane < NT) ? expf(val - m) : 0.f;
        float se = e;
#pragma unroll
        for (int o = 16; o; o >>= 1) se += __shfl_xor_sync(0xffffffffu, se, o);
        if (lane < NT) s->gate[lane] = e / se;
    }
    __syncthreads();

    // h *= gate[t]
    for (int idx = tid; idx < NT*NH; idx += 256) {
        int r = idx >> 7;
        ((float*)s->h)[idx] *= s->gate[r];
    }
    __syncthreads();

    // hn = LayerNorm(h)
    {
        float ng0 = n_g[lane], ng1 = n_g[lane+32], ng2 = n_g[lane+64], ng3 = n_g[lane+96];
        float nb0 = n_b[lane], nb1 = n_b[lane+32], nb2 = n_b[lane+64], nb3 = n_b[lane+96];
        for (int r = wid; r < NT; r += 8) {
            float x0 = s->h[r][lane],    x1 = s->h[r][lane+32];
            float x2 = s->h[r][lane+64], x3 = s->h[r][lane+96];
            float su = x0+x1+x2+x3;
            float sq = x0*x0+x1*x1+x2*x2+x3*x3;
#pragma unroll
            for (int o = 16; o; o >>= 1) {
                su += __shfl_xor_sync(0xffffffffu, su, o);
                sq += __shfl_xor_sync(0xffffffffu, sq, o);
            }
            float mean = su * (1.f/128.f);
            float rstd = rsqrtf(sq*(1.f/128.f) - mean*mean + 1e-5f);
            s->hn[r][lane]    = (x0-mean)*rstd*ng0 + nb0;
            s->hn[r][lane+32] = (x1-mean)*rstd*ng1 + nb1;
            s->hn[r][lane+64] = (x2-mean)*rstd*ng2 + nb2;
            s->hn[r][lane+96] = (x3-mean)*rstd*ng3 + nb3;
        }
    }
    __syncthreads();

    // q,k,v projections
    int cg = tid & 31;
    int rg = tid >> 5;
    int rws[4]; bool rv[4];
#pragma unroll
    for (int i = 0; i < 4; i++) {
        int r = rg + 8*i;
        rv[i] = (r < NT);
        rws[i] = rv[i] ? r : 0;
    }
    small_gemm_qkv(s, Wq, bq, s->q, cg, rg, rws, rv, tid);
    small_gemm_qkv(s, Wk, bk, s->k, cg, rg, rws, rv, tid);
    small_gemm_qkv(s, Wv, bv, s->v, cg, rg, rws, rv, tid);
    __syncthreads();

    // scores: sc[t][u] = scale * <q_t, k_u>
    const float SCALE = 0.08838834764831845f;  // sqrt(1/128)
    for (int p = tid; p < NT*NT; p += 256) {
        int t = p / NT, u = p - t*NT;
        const float4* qa = (const float4*)&s->q[t][0];
        const float4* kb = (const float4*)&s->k[u][0];
        float a = 0.f;
#pragma unroll 8
        for (int j = 0; j < 32; j++) {
            float4 qq = qa[j], kk4 = kb[j];
            a += qq.x*kk4.x + qq.y*kk4.y + qq.z*kk4.z + qq.w*kk4.w;
        }
        s->sc[t][u] = a * SCALE;
    }
    __syncthreads();

    // softmax rows of sc
    for (int r = wid; r < NT; r += 8) {
        float vv = (lane < NT) ? s->sc[r][lane] : -1e30f;
        float m = vv;
#pragma unroll
        for (int o = 16; o; o >>= 1) m = fmaxf(m, __shfl_xor_sync(0xffffffffu, m, o));
        float e = (lane < NT) ? expf(vv - m) : 0.f;
        float se = e;
#pragma unroll
        for (int o = 16; o; o >>= 1) se += __shfl_xor_sync(0xffffffffu, se, o);
        if (lane < NT) s->sc[r][lane] = e / se;
    }
    __syncthreads();

    // o = attn @ v  -> store into hn buffer
    {
        int col = tid & 127, rp = tid >> 7;
#pragma unroll
        for (int j = 0; j < 15; j++) {
            int r = rp + 2*j;
            float a = 0.f;
#pragma unroll
            for (int u = 0; u < NT; u++) a += s->sc[r][u] * s->v[u][col];
            s->hn[r][col] = a;
        }
    }
    __syncthreads();

    // h_out = o @ Wo + bo + h  -> write to global
    {
        float acc[4][4];
#pragma unroll
        for (int i = 0; i < 4; i++) { acc[i][0]=0.f; acc[i][1]=0.f; acc[i][2]=0.f; acc[i][3]=0.f; }
        for (int kc = 0; kc < 4; kc++) {
            for (int idx = tid; idx < 1024; idx += 256) {
                int kk = idx >> 5, jc = idx & 31;
                *(float4*)&s->wbuf[kk][4*jc] = *(const float4*)(Wo + (size_t)(kc*32+kk)*NH + 4*jc);
            }
            __syncthreads();
#pragma unroll 8
            for (int kk = 0; kk < 32; kk++) {
                float4 wv = *(const float4*)&s->wbuf[kk][4*cg];
#pragma unroll
                for (int i = 0; i < 4; i++) {
                    float xv = s->hn[rws[i]][kc*32+kk];
                    acc[i][0] += xv*wv.x; acc[i][1] += xv*wv.y;
                    acc[i][2] += xv*wv.z; acc[i][3] += xv*wv.w;
                }
            }
            __syncthreads();
        }
        float4 bb = *(const float4*)(bo + 4*cg);
#pragma unroll
        for (int i = 0; i < 4; i++) {
            if (rv[i]) {
                int r = rws[i];
                float4 o4;
                o4.x = acc[i][0]+bb.x + s->h[r][4*cg+0];
                o4.y = acc[i][1]+bb.y + s->h[r][4*cg+1];
                o4.z = acc[i][2]+bb.z + s->h[r][4*cg+2];
                o4.w = acc[i][3]+bb.w + s->h[r][4*cg+3];
                *(float4*)(hg + (size_t)r*NH + 4*cg) = o4;
            }
        }
    }
}

// ---------------------------------------------------------------------------
// Kernel C: out = h @ W2 + b2   [47280,128]@[128,1024]
// Tile: 48 rows x 128 cols, grid (985, 8).
// ---------------------------------------------------------------------------
__global__ __launch_bounds__(256) void k_gemm2(
    const float* __restrict__ W2, const float* __restrict__ b2,
    float* __restrict__ out)
{
    __shared__ float hs[48][128];
    __shared__ float ws[32][128];
    int tid = threadIdx.x;
    int cg = tid & 31;
    int rg = tid >> 5;
    int row0 = blockIdx.x * 48;
    int n0   = blockIdx.y * 128;

    for (int idx = tid; idx < 48*32; idx += 256)
        ((float4*)hs)[idx] = ((const float4*)(g_h + (size_t)row0*NH))[idx];

    float acc[6][4];
#pragma unroll
    for (int i = 0; i < 6; i++) { acc[i][0]=0.f; acc[i][1]=0.f; acc[i][2]=0.f; acc[i][3]=0.f; }

    for (int kc = 0; kc < 4; kc++) {
        for (int idx = tid; idx < 1024; idx += 256) {
            int kk = idx >> 5, jc = idx & 31;
            *(float4*)&ws[kk][4*jc] = *(const float4*)(W2 + (size_t)(kc*32+kk)*ND + n0 + 4*jc);
        }
        __syncthreads();
#pragma unroll 8
        for (int kk = 0; kk < 32; kk++) {
            float4 wv = *(const float4*)&ws[kk][4*cg];
#pragma unroll
            for (int i = 0; i < 6; i++) {
                float xv = hs[rg*6+i][kc*32+kk];
                acc[i][0] += xv*wv.x; acc[i][1] += xv*wv.y;
                acc[i][2] += xv*wv.z; acc[i][3] += xv*wv.w;
            }
        }
        __syncthreads();
    }

    float4 bb = *(const float4*)(b2 + n0 + 4*cg);
#pragma unroll
    for (int i = 0; i < 6; i++) {
        int row = row0 + rg*6 + i;
        float4 o4;
        o4.x = acc[i][0]+bb.x; o4.y = acc[i][1]+bb.y;
        o4.z = acc[i][2]+bb.z; o4.w = acc[i][3]+bb.w;
        *(float4*)(out + (size_t)row*ND + n0 + 4*cg) = o4;
    }
}

// ---------------------------------------------------------------------------
extern "C" void kernel_launch(void* const* d_in, const int* in_sizes, int n_in,
                              void* d_out, int out_size)
{
    const float* x    = (const float*)d_in[0];
    const float* W1   = (const float*)d_in[1];
    const float* b1   = (const float*)d_in[2];
    const float* ln_g = (const float*)d_in[3];
    const float* ln_b = (const float*)d_in[4];
    const float* T_W  = (const float*)d_in[5];
    const float* T_b  = (const float*)d_in[6];
    const float* Wq   = (const float*)d_in[7];
    const float* bq   = (const float*)d_in[8];
    const float* Wk   = (const float*)d_in[9];
    const float* bk   = (const float*)d_in[10];
    const float* Wv   = (const float*)d_in[11];
    const float* bv   = (const float*)d_in[12];
    const float* Wo   = (const float*)d_in[13];
    const float* bo   = (const float*)d_in[14];
    const float* n_g  = (const float*)d_in[15];
    const float* n_b  = (const float*)d_in[16];
    const float* W2   = (const float*)d_in[17];
    const float* b2   = (const float*)d_in[18];
    float* out = (float*)d_out;

    static int smem_set = 0;
    (void)smem_set;
    cudaFuncSetAttribute(k_attn, cudaFuncAttributeMaxDynamicSharedMemorySize,
                         (int)sizeof(SmemC));

    k_gemm1_ln<<<NM/48, 256>>>(x, W1, b1, ln_g, ln_b);
    k_attn<<<NB, 256, sizeof(SmemC)>>>(T_W, T_b, Wq, bq, Wk, bk, Wv, bv,
                                       Wo, bo, n_g, n_b);
    k_gemm2<<<dim3(NM/48, 8), 256>>>(W2, b2, out);
}

// round 8
// speedup vs baseline: 1.5851x; 1.5851x over previous
#include <cuda_runtime.h>
#include <math.h>
#include <stdint.h>

#define NB 1576
#define NT 30
#define ND 1024
#define NH 128
#define NM (NB*NT)   // 47280

// scratch
__device__ float g_h[(size_t)NM * NH];
__device__ float g_W1r[(size_t)ND * NH];   // W1 tf32-rounded, same [K=1024][N=128] layout
__device__ float g_W2r[(size_t)NH * ND];   // W2 tf32-rounded, same [K=128][N=1024] layout

// ---------------------------------------------------------------------------
// helpers
// ---------------------------------------------------------------------------
__device__ __forceinline__ uint32_t smem_u32(const void* p) {
    uint32_t a;
    asm("{ .reg .u64 t; cvta.to.shared.u64 t, %1; cvt.u32.u64 %0, t; }" : "=r"(a) : "l"(p));
    return a;
}
__device__ __forceinline__ uint32_t f2tf32(float f) {
    uint32_t r; asm("cvt.rna.tf32.f32 %0, %1;" : "=r"(r) : "f"(f)); return r;
}
__device__ __forceinline__ void sts128(uint32_t a, uint32_t x, uint32_t y, uint32_t z, uint32_t w) {
    asm volatile("st.shared.v4.b32 [%0], {%1,%2,%3,%4};" :: "r"(a), "r"(x), "r"(y), "r"(z), "r"(w));
}
__device__ __forceinline__ uint32_t lds_u(uint32_t a) {
    uint32_t v; asm volatile("ld.shared.b32 %0, [%1];" : "=r"(v) : "r"(a)); return v;
}
__device__ __forceinline__ void cp16(uint32_t dst, const void* src) {
    asm volatile("cp.async.cg.shared.global [%0], [%1], 16;" :: "r"(dst), "l"(src));
}
#define CP_COMMIT() asm volatile("cp.async.commit_group;" ::: "memory")
#define CP_WAIT0()  asm volatile("cp.async.wait_group 0;" ::: "memory")

// ---------------------------------------------------------------------------
// SMEM for the mma.sync GEMMs
//  A[buf]: [128][36] floats (pad 4 -> conflict-free frag loads, 16B rows)
//  B[buf]: [32][136] floats (pad 8 -> conflict-free frag loads)
//  epilogue reuses the union as epi[128][132]
// ---------------------------------------------------------------------------
#define LDA_S 36
#define LDB_S 136
#define LDE_S 132
struct SmemG {
    union {
        struct {
            float A[2][128 * LDA_S];
            float B[2][32 * LDB_S];
        } mm;
        float epi[128 * LDE_S];
    } u;
    float parb[128];
    float parg[128];
    float parbt[128];
    float mean[128];
    float rstd[128];
};

// ---------------------------------------------------------------------------
// elementwise tf32 round of weights
// ---------------------------------------------------------------------------
__global__ void k_round(const float* __restrict__ in, float* __restrict__ out, int n) {
    int i = blockIdx.x * 256 + threadIdx.x;
    if (i < n) out[i] = __uint_as_float(f2tf32(in[i]));
}

// ---------------------------------------------------------------------------
// mainloop building blocks
// ---------------------------------------------------------------------------
__device__ __forceinline__ void ldgA(const float* __restrict__ Ag, int ldA,
                                     int row0, int k0, int tid, float4 v[4]) {
#pragma unroll
    for (int q = 0; q < 4; q++) {
        int idx = tid + 256 * q;
        int r = idx >> 3, j = idx & 7;
        int row = row0 + r;
        float4 t = make_float4(0.f, 0.f, 0.f, 0.f);
        if (row < NM) t = *(const float4*)(Ag + (size_t)row * ldA + k0 + j * 4);
        v[q] = t;
    }
}
__device__ __forceinline__ void stsA(uint32_t As, int tid, const float4 v[4]) {
#pragma unroll
    for (int q = 0; q < 4; q++) {
        int idx = tid + 256 * q;
        int r = idx >> 3, j = idx & 7;
        sts128(As + (r * LDA_S + j * 4) * 4,
               f2tf32(v[q].x), f2tf32(v[q].y), f2tf32(v[q].z), f2tf32(v[q].w));
    }
}
__device__ __forceinline__ void cpB(uint32_t Bs, const float* __restrict__ Bg,
                                    int ldB, int bn0, int k0, int tid) {
#pragma unroll
    for (int q = 0; q < 4; q++) {
        int idx = tid + 256 * q;
        int kk = idx >> 5, jc = idx & 31;
        cp16(Bs + (kk * LDB_S + jc * 4) * 4,
             Bg + (size_t)(k0 + kk) * ldB + bn0 + jc * 4);
    }
}

__device__ __forceinline__ void mm_compute(uint32_t As, uint32_t Bs,
                                           int lane, int wm, int wn,
                                           float acc[4][4][4]) {
    int tr = lane >> 2, tc = lane & 3;
#pragma unroll
    for (int ks = 0; ks < 4; ks++) {
        int k0 = ks * 8;
        uint32_t af[4][4];
#pragma unroll
        for (int mt = 0; mt < 4; mt++) {
            int row = wm + mt * 16 + tr;
            uint32_t b0 = As + (row * LDA_S + k0 + tc) * 4;
            af[mt][0] = lds_u(b0);
            af[mt][1] = lds_u(b0 + 8 * LDA_S * 4);
            af[mt][2] = lds_u(b0 + 16);
            af[mt][3] = lds_u(b0 + 8 * LDA_S * 4 + 16);
        }
        uint32_t bf[4][2];
#pragma unroll
        for (int nt = 0; nt < 4; nt++) {
            int col = wn + nt * 8 + tr;
            uint32_t b0 = Bs + ((k0 + tc) * LDB_S + col) * 4;
            bf[nt][0] = lds_u(b0);
            bf[nt][1] = lds_u(b0 + 4 * LDB_S * 4);
        }
#pragma unroll
        for (int mt = 0; mt < 4; mt++)
#pragma unroll
            for (int nt = 0; nt < 4; nt++)
                asm volatile(
                    "mma.sync.aligned.m16n8k8.row.col.f32.tf32.tf32.f32 "
                    "{%0,%1,%2,%3}, {%4,%5,%6,%7}, {%8,%9}, {%0,%1,%2,%3};"
                    : "+f"(acc[mt][nt][0]), "+f"(acc[mt][nt][1]),
                      "+f"(acc[mt][nt][2]), "+f"(acc[mt][nt][3])
                    : "r"(af[mt][0]), "r"(af[mt][1]), "r"(af[mt][2]), "r"(af[mt][3]),
                      "r"(bf[nt][0]), "r"(bf[nt][1]));
    }
}

// ---------------------------------------------------------------------------
// GEMM1: h = LayerNorm(x @ W1 + b1)    [47280,1024]@[1024,128]
// ---------------------------------------------------------------------------
__global__ __launch_bounds__(256) void k1_mma(
    const float* __restrict__ x, const float* __restrict__ b1,
    const float* __restrict__ ln_g, const float* __restrict__ ln_b)
{
    extern __shared__ char smraw[];
    SmemG* s = (SmemG*)smraw;
    int tid = threadIdx.x;
    int lane = tid & 31, wid = tid >> 5;
    int row0 = blockIdx.x * 128;
    int wm = (wid >> 2) * 64, wn = (wid & 3) * 32;
    const float* W1r = g_W1r;

    if (tid < 128) {
        s->parb[tid]  = b1[tid];
        s->parg[tid]  = ln_g[tid];
        s->parbt[tid] = ln_b[tid];
    }
    uint32_t aA[2], aB[2];
    aA[0] = smem_u32(&s->u.mm.A[0][0]); aA[1] = smem_u32(&s->u.mm.A[1][0]);
    aB[0] = smem_u32(&s->u.mm.B[0][0]); aB[1] = smem_u32(&s->u.mm.B[1][0]);

    float acc[4][4][4];
#pragma unroll
    for (int a = 0; a < 4; a++)
#pragma unroll
        for (int b = 0; b < 4; b++) { acc[a][b][0]=0.f; acc[a][b][1]=0.f; acc[a][b][2]=0.f; acc[a][b][3]=0.f; }

    const int NIT = ND / 32;  // 32
    float4 vr[4];
    ldgA(x, ND, row0, 0, tid, vr);
    cpB(aB[0], W1r, NH, 0, 0, tid);
    CP_COMMIT();
    stsA(aA[0], tid, vr);
    CP_WAIT0();
    __syncthreads();

    int buf = 0;
    for (int it = 0; it < NIT; it++) {
        bool pf = (it + 1 < NIT);
        if (pf) {
            ldgA(x, ND, row0, (it + 1) * 32, tid, vr);
            cpB(aB[buf ^ 1], W1r, NH, 0, (it + 1) * 32, tid);
            CP_COMMIT();
        }
        mm_compute(aA[buf], aB[buf], lane, wm, wn, acc);
        if (pf) stsA(aA[buf ^ 1], tid, vr);
        CP_WAIT0();
        __syncthreads();
        buf ^= 1;
    }

    // ---- epilogue: bias -> epi smem, LN stats, normalize + store ----
    int tr = lane >> 2, tc = lane & 3;
    float* epi = s->u.epi;
#pragma unroll
    for (int mt = 0; mt < 4; mt++) {
#pragma unroll
        for (int nt = 0; nt < 4; nt++) {
            int row = wm + mt * 16 + tr;
            int col = wn + nt * 8 + 2 * tc;
            float bb0 = s->parb[col], bb1 = s->parb[col + 1];
            epi[row * LDE_S + col]           = acc[mt][nt][0] + bb0;
            epi[row * LDE_S + col + 1]       = acc[mt][nt][1] + bb1;
            epi[(row + 8) * LDE_S + col]     = acc[mt][nt][2] + bb0;
            epi[(row + 8) * LDE_S + col + 1] = acc[mt][nt][3] + bb1;
        }
    }
    __syncthreads();

    for (int r = wid; r < 128; r += 8) {
        float x0 = epi[r * LDE_S + lane];
        float x1 = epi[r * LDE_S + lane + 32];
        float x2 = epi[r * LDE_S + lane + 64];
        float x3 = epi[r * LDE_S + lane + 96];
        float su = x0 + x1 + x2 + x3;
        float sq = x0 * x0 + x1 * x1 + x2 * x2 + x3 * x3;
#pragma unroll
        for (int o = 16; o; o >>= 1) {
            su += __shfl_xor_sync(0xffffffffu, su, o);
            sq += __shfl_xor_sync(0xffffffffu, sq, o);
        }
        float mean = su * (1.f / 128.f);
        float var  = sq * (1.f / 128.f) - mean * mean;
        if (lane == 0) {
            s->mean[r] = mean;
            s->rstd[r] = rsqrtf(fmaxf(var, 0.f) + 1e-5f);
        }
    }
    __syncthreads();

#pragma unroll
    for (int q = 0; q < 16; q++) {
        int idx = tid + 256 * q;
        int r = idx >> 5, c4 = idx & 31;
        int row = row0 + r;
        if (row < NM) {
            float4 v = *(float4*)&epi[r * LDE_S + 4 * c4];
            float mean = s->mean[r], rstd = s->rstd[r];
            float4 gv = *(float4*)&s->parg[4 * c4];
            float4 bv = *(float4*)&s->parbt[4 * c4];
            float4 o;
            o.x = (v.x - mean) * rstd * gv.x + bv.x;
            o.y = (v.y - mean) * rstd * gv.y + bv.y;
            o.z = (v.z - mean) * rstd * gv.z + bv.z;
            o.w = (v.w - mean) * rstd * gv.w + bv.w;
            *(float4*)(g_h + (size_t)row * NH + 4 * c4) = o;
        }
    }
}

// ---------------------------------------------------------------------------
// GEMM2: out = h @ W2 + b2     [47280,128]@[128,1024], grid (370, 8)
// ---------------------------------------------------------------------------
__global__ __launch_bounds__(256) void k2_mma(
    const float* __restrict__ b2, float* __restrict__ out)
{
    extern __shared__ char smraw[];
    SmemG* s = (SmemG*)smraw;
    int tid = threadIdx.x;
    int lane = tid & 31, wid = tid >> 5;
    int row0 = blockIdx.x * 128;
    int n0   = blockIdx.y * 128;
    int wm = (wid >> 2) * 64, wn = (wid & 3) * 32;
    const float* W2r = g_W2r;

    if (tid < 128) s->parb[tid] = b2[n0 + tid];
    uint32_t aA[2], aB[2];
    aA[0] = smem_u32(&s->u.mm.A[0][0]); aA[1] = smem_u32(&s->u.mm.A[1][0]);
    aB[0] = smem_u32(&s->u.mm.B[0][0]); aB[1] = smem_u32(&s->u.mm.B[1][0]);

    float acc[4][4][4];
#pragma unroll
    for (int a = 0; a < 4; a++)
#pragma unroll
        for (int b = 0; b < 4; b++) { acc[a][b][0]=0.f; acc[a][b][1]=0.f; acc[a][b][2]=0.f; acc[a][b][3]=0.f; }

    const int NIT = NH / 32;  // 4
    float4 vr[4];
    ldgA(g_h, NH, row0, 0, tid, vr);
    cpB(aB[0], W2r, ND, n0, 0, tid);
    CP_COMMIT();
    stsA(aA[0], tid, vr);
    CP_WAIT0();
    __syncthreads();

    int buf = 0;
    for (int it = 0; it < NIT; it++) {
        bool pf = (it + 1 < NIT);
        if (pf) {
            ldgA(g_h, NH, row0, (it + 1) * 32, tid, vr);
            cpB(aB[buf ^ 1], W2r, ND, n0, (it + 1) * 32, tid);
            CP_COMMIT();
        }
        mm_compute(aA[buf], aB[buf], lane, wm, wn, acc);
        if (pf) stsA(aA[buf ^ 1], tid, vr);
        CP_WAIT0();
        __syncthreads();
        buf ^= 1;
    }

    // ---- epilogue: bias + direct coalesced-enough float2 stores ----
    int tr = lane >> 2, tc = lane & 3;
#pragma unroll
    for (int mt = 0; mt < 4; mt++) {
#pragma unroll
        for (int nt = 0; nt < 4; nt++) {
            int colL = wn + nt * 8 + 2 * tc;
            int col  = n0 + colL;
            float bb0 = s->parb[colL], bb1 = s->parb[colL + 1];
            int row = row0 + wm + mt * 16 + tr;
            if (row < NM) {
                float2 v0 = make_float2(acc[mt][nt][0] + bb0, acc[mt][nt][1] + bb1);
                *(float2*)(out + (size_t)row * ND + col) = v0;
            }
            if (row + 8 < NM) {
                float2 v1 = make_float2(acc[mt][nt][2] + bb0, acc[mt][nt][3] + bb1);
                *(float2*)(out + (size_t)(row + 8) * ND + col) = v1;
            }
        }
    }
}

// ---------------------------------------------------------------------------
// Kernel B: per-batch FRU gate + LN + single-head attention (fp32, unchanged)
// ---------------------------------------------------------------------------
struct SmemC {
    float h [32][128];
    float hn[32][128];
    float q [32][128];
    float k [32][128];
    float v [32][128];
    float wbuf[32][128];
    float sc[30][32];
    float gate[32];
    float rowm[32];
};

__device__ __forceinline__ void small_gemm_qkv(
    SmemC* s, const float* __restrict__ W, const float* __restrict__ bias,
    float (*outp)[128], int cg, int rg, const int* rws, const bool* rv, int tid)
{
    float acc[4][4];
#pragma unroll
    for (int i = 0; i < 4; i++) { acc[i][0]=0.f; acc[i][1]=0.f; acc[i][2]=0.f; acc[i][3]=0.f; }
    for (int kc = 0; kc < 4; kc++) {
        for (int idx = tid; idx < 1024; idx += 256) {
            int kk = idx >> 5, jc = idx & 31;
            *(float4*)&s->wbuf[kk][4*jc] = *(const float4*)(W + (size_t)(kc*32+kk)*NH + 4*jc);
        }
        __syncthreads();
#pragma unroll 8
        for (int kk = 0; kk < 32; kk++) {
            float4 wv = *(const float4*)&s->wbuf[kk][4*cg];
#pragma unroll
            for (int i = 0; i < 4; i++) {
                float xv = s->hn[rws[i]][kc*32+kk];
                acc[i][0] += xv*wv.x; acc[i][1] += xv*wv.y;
                acc[i][2] += xv*wv.z; acc[i][3] += xv*wv.w;
            }
        }
        __syncthreads();
    }
    float4 bb = *(const float4*)(bias + 4*cg);
#pragma unroll
    for (int i = 0; i < 4; i++) {
        if (rv[i]) {
            float4 o4;
            o4.x = acc[i][0]+bb.x; o4.y = acc[i][1]+bb.y;
            o4.z = acc[i][2]+bb.z; o4.w = acc[i][3]+bb.w;
            *(float4*)&outp[rws[i]][4*cg] = o4;
        }
    }
}

__global__ __launch_bounds__(256) void k_attn(
    const float* __restrict__ T_W, const float* __restrict__ T_b,
    const float* __restrict__ Wq, const float* __restrict__ bq,
    const float* __restrict__ Wk, const float* __restrict__ bk,
    const float* __restrict__ Wv, const float* __restrict__ bv,
    const float* __restrict__ Wo, const float* __restrict__ bo,
    const float* __restrict__ n_g, const float* __restrict__ n_b)
{
    extern __shared__ char smem_raw[];
    SmemC* s = (SmemC*)smem_raw;
    int tid = threadIdx.x;
    int lane = tid & 31, wid = tid >> 5;
    int b = blockIdx.x;
    float* hg = g_h + (size_t)b * NT * NH;

    for (int idx = tid; idx < NT*NH/4; idx += 256)
        ((float4*)&s->h[0][0])[idx] = ((const float4*)hg)[idx];
    __syncthreads();

    for (int r = wid; r < NT; r += 8) {
        float a = s->h[r][lane] + s->h[r][lane+32] + s->h[r][lane+64] + s->h[r][lane+96];
#pragma unroll
        for (int o = 16; o; o >>= 1) a += __shfl_xor_sync(0xffffffffu, a, o);
        if (lane == 0) s->rowm[r] = a * (1.f/128.f);
    }
    __syncthreads();

    if (wid == 0) {
        float val = -1e30f;
        if (lane < NT) {
            float a = T_b[lane];
            for (int u = 0; u < NT; u++) a += s->rowm[u] * T_W[u*NT + lane];
            val = a;
        }
        float m = val;
#pragma unroll
        for (int o = 16; o; o >>= 1) m = fmaxf(m, __shfl_xor_sync(0xffffffffu, m, o));
        float e = (lane < NT) ? expf(val - m) : 0.f;
        float se = e;
#pragma unroll
        for (int o = 16; o; o >>= 1) se += __shfl_xor_sync(0xffffffffu, se, o);
        if (lane < NT) s->gate[lane] = e / se;
    }
    __syncthreads();

    for (int idx = tid; idx < NT*NH; idx += 256) {
        int r = idx >> 7;
        ((float*)s->h)[idx] *= s->gate[r];
    }
    __syncthreads();

    {
        float ng0 = n_g[lane], ng1 = n_g[lane+32], ng2 = n_g[lane+64], ng3 = n_g[lane+96];
        float nb0 = n_b[lane], nb1 = n_b[lane+32], nb2 = n_b[lane+64], nb3 = n_b[lane+96];
        for (int r = wid; r < NT; r += 8) {
            float x0 = s->h[r][lane],    x1 = s->h[r][lane+32];
            float x2 = s->h[r][lane+64], x3 = s->h[r][lane+96];
            float su = x0+x1+x2+x3;
            float sq = x0*x0+x1*x1+x2*x2+x3*x3;
#pragma unroll
            for (int o = 16; o; o >>= 1) {
                su += __shfl_xor_sync(0xffffffffu, su, o);
                sq += __shfl_xor_sync(0xffffffffu, sq, o);
            }
            float mean = su * (1.f/128.f);
            float rstd = rsqrtf(sq*(1.f/128.f) - mean*mean + 1e-5f);
            s->hn[r][lane]    = (x0-mean)*rstd*ng0 + nb0;
            s->hn[r][lane+32] = (x1-mean)*rstd*ng1 + nb1;
            s->hn[r][lane+64] = (x2-mean)*rstd*ng2 + nb2;
            s->hn[r][lane+96] = (x3-mean)*rstd*ng3 + nb3;
        }
    }
    __syncthreads();

    int cg = tid & 31;
    int rg = tid >> 5;
    int rws[4]; bool rv[4];
#pragma unroll
    for (int i = 0; i < 4; i++) {
        int r = rg + 8*i;
        rv[i] = (r < NT);
        rws[i] = rv[i] ? r : 0;
    }
    small_gemm_qkv(s, Wq, bq, s->q, cg, rg, rws, rv, tid);
    small_gemm_qkv(s, Wk, bk, s->k, cg, rg, rws, rv, tid);
    small_gemm_qkv(s, Wv, bv, s->v, cg, rg, rws, rv, tid);
    __syncthreads();

    const float SCALE = 0.08838834764831845f;
    for (int p = tid; p < NT*NT; p += 256) {
        int t = p / NT, u = p - t*NT;
        const float4* qa = (const float4*)&s->q[t][0];
        const float4* kb = (const float4*)&s->k[u][0];
        float a = 0.f;
#pragma unroll 8
        for (int j = 0; j < 32; j++) {
            float4 qq = qa[j], kk4 = kb[j];
            a += qq.x*kk4.x + qq.y*kk4.y + qq.z*kk4.z + qq.w*kk4.w;
        }
        s->sc[t][u] = a * SCALE;
    }
    __syncthreads();

    for (int r = wid; r < NT; r += 8) {
        float vv = (lane < NT) ? s->sc[r][lane] : -1e30f;
        float m = vv;
#pragma unroll
        for (int o = 16; o; o >>= 1) m = fmaxf(m, __shfl_xor_sync(0xffffffffu, m, o));
        float e = (lane < NT) ? expf(vv - m) : 0.f;
        float se = e;
#pragma unroll
        for (int o = 16; o; o >>= 1) se += __shfl_xor_sync(0xffffffffu, se, o);
        if (lane < NT) s->sc[r][lane] = e / se;
    }
    __syncthreads();

    {
        int col = tid & 127, rp = tid >> 7;
#pragma unroll
        for (int j = 0; j < 15; j++) {
            int r = rp + 2*j;
            float a = 0.f;
#pragma unroll
            for (int u = 0; u < NT; u++) a += s->sc[r][u] * s->v[u][col];
            s->hn[r][col] = a;
        }
    }
    __syncthreads();

    {
        float acc[4][4];
#pragma unroll
        for (int i = 0; i < 4; i++) { acc[i][0]=0.f; acc[i][1]=0.f; acc[i][2]=0.f; acc[i][3]=0.f; }
        for (int kc = 0; kc < 4; kc++) {
            for (int idx = tid; idx < 1024; idx += 256) {
                int kk = idx >> 5, jc = idx & 31;
                *(float4*)&s->wbuf[kk][4*jc] = *(const float4*)(Wo + (size_t)(kc*32+kk)*NH + 4*jc);
            }
            __syncthreads();
#pragma unroll 8
            for (int kk = 0; kk < 32; kk++) {
                float4 wv = *(const float4*)&s->wbuf[kk][4*cg];
#pragma unroll
                for (int i = 0; i < 4; i++) {
                    float xv = s->hn[rws[i]][kc*32+kk];
                    acc[i][0] += xv*wv.x; acc[i][1] += xv*wv.y;
                    acc[i][2] += xv*wv.z; acc[i][3] += xv*wv.w;
                }
            }
            __syncthreads();
        }
        float4 bb = *(const float4*)(bo + 4*cg);
#pragma unroll
        for (int i = 0; i < 4; i++) {
            if (rv[i]) {
                int r = rws[i];
                float4 o4;
                o4.x = acc[i][0]+bb.x + s->h[r][4*cg+0];
                o4.y = acc[i][1]+bb.y + s->h[r][4*cg+1];
                o4.z = acc[i][2]+bb.z + s->h[r][4*cg+2];
                o4.w = acc[i][3]+bb.w + s->h[r][4*cg+3];
                *(float4*)(hg + (size_t)r*NH + 4*cg) = o4;
            }
        }
    }
}

// ---------------------------------------------------------------------------
extern "C" void kernel_launch(void* const* d_in, const int* in_sizes, int n_in,
                              void* d_out, int out_size)
{
    const float* x    = (const float*)d_in[0];
    const float* W1   = (const float*)d_in[1];
    const float* b1   = (const float*)d_in[2];
    const float* ln_g = (const float*)d_in[3];
    const float* ln_b = (const float*)d_in[4];
    const float* T_W  = (const float*)d_in[5];
    const float* T_b  = (const float*)d_in[6];
    const float* Wq   = (const float*)d_in[7];
    const float* bq   = (const float*)d_in[8];
    const float* Wk   = (const float*)d_in[9];
    const float* bk   = (const float*)d_in[10];
    const float* Wv   = (const float*)d_in[11];
    const float* bv   = (const float*)d_in[12];
    const float* Wo   = (const float*)d_in[13];
    const float* bo   = (const float*)d_in[14];
    const float* n_g  = (const float*)d_in[15];
    const float* n_b  = (const float*)d_in[16];
    const float* W2   = (const float*)d_in[17];
    const float* b2   = (const float*)d_in[18];
    float* out = (float*)d_out;

    int dynG = (int)sizeof(SmemG);
    cudaFuncSetAttribute(k1_mma, cudaFuncAttributeMaxDynamicSharedMemorySize, dynG);
    cudaFuncSetAttribute(k2_mma, cudaFuncAttributeMaxDynamicSharedMemorySize, dynG);
    cudaFuncSetAttribute(k_attn, cudaFuncAttributeMaxDynamicSharedMemorySize,
                         (int)sizeof(SmemC));

    float* w1r; cudaGetSymbolAddress((void**)&w1r, g_W1r);
    float* w2r; cudaGetSymbolAddress((void**)&w2r, g_W2r);

    k_round<<<(ND * NH + 255) / 256, 256>>>(W1, w1r, ND * NH);
    k_round<<<(NH * ND + 255) / 256, 256>>>(W2, w2r, NH * ND);

    k1_mma<<<(NM + 127) / 128, 256, dynG>>>(x, b1, ln_g, ln_b);
    k_attn<<<NB, 256, sizeof(SmemC)>>>(T_W, T_b, Wq, bq, Wk, bk, Wv, bv,
                                       Wo, bo, n_g, n_b);
    k2_mma<<<dim3((NM + 127) / 128, ND / 128), 256, dynG>>>(b2, out);
}

// round 10
// speedup vs baseline: 2.6813x; 1.6916x over previous
#include <cuda_runtime.h>
#include <math.h>
#include <stdint.h>

#define NB 1576
#define NT 30
#define ND 1024
#define NH 128
#define NM (NB*NT)   // 47280

// scratch
__device__ float g_h  [(size_t)NM * NH];
__device__ float g_hg [(size_t)NM * NH];   // gated h (residual)
__device__ float g_hn [(size_t)NM * NH];   // LN(gated h)
__device__ float g_o  [(size_t)NM * NH];   // attn @ v
__device__ float g_qkv[(size_t)NM * 384];  // q|k|v
__device__ float g_W1r[(size_t)ND * NH];
__device__ float g_W2r[(size_t)NH * ND];
__device__ float g_Wor[(size_t)NH * NH];
__device__ float g_Wqkvr[(size_t)NH * 384];
__device__ float g_bqkv[384];

// ---------------------------------------------------------------------------
// helpers
// ---------------------------------------------------------------------------
__device__ __forceinline__ uint32_t smem_u32(const void* p) {
    uint32_t a;
    asm("{ .reg .u64 t; cvta.to.shared.u64 t, %1; cvt.u32.u64 %0, t; }" : "=r"(a) : "l"(p));
    return a;
}
__device__ __forceinline__ uint32_t f2tf32(float f) {
    uint32_t r; asm("cvt.rna.tf32.f32 %0, %1;" : "=r"(r) : "f"(f)); return r;
}
__device__ __forceinline__ void sts128(uint32_t a, uint32_t x, uint32_t y, uint32_t z, uint32_t w) {
    asm volatile("st.shared.v4.b32 [%0], {%1,%2,%3,%4};" :: "r"(a), "r"(x), "r"(y), "r"(z), "r"(w));
}
__device__ __forceinline__ uint32_t lds_u(uint32_t a) {
    uint32_t v; asm volatile("ld.shared.b32 %0, [%1];" : "=r"(v) : "r"(a)); return v;
}
__device__ __forceinline__ void cp16(uint32_t dst, const void* src) {
    asm volatile("cp.async.cg.shared.global [%0], [%1], 16;" :: "r"(dst), "l"(src));
}
#define CP_COMMIT() asm volatile("cp.async.commit_group;" ::: "memory")
#define CP_WAIT0()  asm volatile("cp.async.wait_group 0;" ::: "memory")

// ---------------------------------------------------------------------------
// GEMM smem
// ---------------------------------------------------------------------------
#define LDA_S 36
#define LDB_S 136
#define LDE_S 132
struct SmemG {
    union {
        struct {
            float A[2][128 * LDA_S];
            float B[2][32 * LDB_S];
        } mm;
        float epi[128 * LDE_S];
    } u;
    float parb[128];
    float parg[128];
    float parbt[128];
    float mean[128];
    float rstd[128];
};

__global__ void k_round(const float* __restrict__ in, float* __restrict__ out, int n) {
    int i = blockIdx.x * 256 + threadIdx.x;
    if (i < n) out[i] = __uint_as_float(f2tf32(in[i]));
}

__global__ void k_pack_qkv(const float* __restrict__ Wq, const float* __restrict__ Wk,
                           const float* __restrict__ Wv, const float* __restrict__ bq,
                           const float* __restrict__ bk, const float* __restrict__ bv) {
    int i = blockIdx.x * 256 + threadIdx.x;
    if (i < 3 * NH * NH) {
        int m = i / (NH * NH);
        int r = (i / NH) % NH;
        int n = i % NH;
        const float* W = (m == 0) ? Wq : (m == 1) ? Wk : Wv;
        g_Wqkvr[(size_t)r * 384 + m * NH + n] = __uint_as_float(f2tf32(W[(size_t)r * NH + n]));
    }
    if (i < 384) {
        int m = i / NH, n = i % NH;
        const float* bb = (m == 0) ? bq : (m == 1) ? bk : bv;
        g_bqkv[i] = bb[n];
    }
}

// ---------------------------------------------------------------------------
// mainloop building blocks
// ---------------------------------------------------------------------------
__device__ __forceinline__ void ldgA(const float* __restrict__ Ag, int ldA,
                                     int row0, int k0, int tid, float4 v[4]) {
#pragma unroll
    for (int q = 0; q < 4; q++) {
        int idx = tid + 256 * q;
        int r = idx >> 3, j = idx & 7;
        int row = row0 + r;
        float4 t = make_float4(0.f, 0.f, 0.f, 0.f);
        if (row < NM) t = *(const float4*)(Ag + (size_t)row * ldA + k0 + j * 4);
        v[q] = t;
    }
}
__device__ __forceinline__ void stsA(uint32_t As, int tid, const float4 v[4]) {
#pragma unroll
    for (int q = 0; q < 4; q++) {
        int idx = tid + 256 * q;
        int r = idx >> 3, j = idx & 7;
        sts128(As + (r * LDA_S + j * 4) * 4,
               f2tf32(v[q].x), f2tf32(v[q].y), f2tf32(v[q].z), f2tf32(v[q].w));
    }
}
__device__ __forceinline__ void cpB(uint32_t Bs, const float* __restrict__ Bg,
                                    int ldB, int bn0, int k0, int tid) {
#pragma unroll
    for (int q = 0; q < 4; q++) {
        int idx = tid + 256 * q;
        int kk = idx >> 5, jc = idx & 31;
        cp16(Bs + (kk * LDB_S + jc * 4) * 4,
             Bg + (size_t)(k0 + kk) * ldB + bn0 + jc * 4);
    }
}

__device__ __forceinline__ void mm_compute(uint32_t As, uint32_t Bs,
                                           int lane, int wm, int wn,
                                           float acc[4][4][4]) {
    int tr = lane >> 2, tc = lane & 3;
#pragma unroll
    for (int ks = 0; ks < 4; ks++) {
        int k0 = ks * 8;
        uint32_t af[4][4];
#pragma unroll
        for (int mt = 0; mt < 4; mt++) {
            int row = wm + mt * 16 + tr;
            uint32_t b0 = As + (row * LDA_S + k0 + tc) * 4;
            af[mt][0] = lds_u(b0);
            af[mt][1] = lds_u(b0 + 8 * LDA_S * 4);
            af[mt][2] = lds_u(b0 + 16);
            af[mt][3] = lds_u(b0 + 8 * LDA_S * 4 + 16);
        }
        uint32_t bf[4][2];
#pragma unroll
        for (int nt = 0; nt < 4; nt++) {
            int col = wn + nt * 8 + tr;
            uint32_t b0 = Bs + ((k0 + tc) * LDB_S + col) * 4;
            bf[nt][0] = lds_u(b0);
            bf[nt][1] = lds_u(b0 + 4 * LDB_S * 4);
        }
#pragma unroll
        for (int mt = 0; mt < 4; mt++)
#pragma unroll
            for (int nt = 0; nt < 4; nt++)
                asm volatile(
                    "mma.sync.aligned.m16n8k8.row.col.f32.tf32.tf32.f32 "
                    "{%0,%1,%2,%3}, {%4,%5,%6,%7}, {%8,%9}, {%0,%1,%2,%3};"
                    : "+f"(acc[mt][nt][0]), "+f"(acc[mt][nt][1]),
                      "+f"(acc[mt][nt][2]), "+f"(acc[mt][nt][3])
                    : "r"(af[mt][0]), "r"(af[mt][1]), "r"(af[mt][2]), "r"(af[mt][3]),
                      "r"(bf[nt][0]), "r"(bf[nt][1]));
    }
}

#define ACC_INIT(acc) \
    _Pragma("unroll") for (int a_ = 0; a_ < 4; a_++) \
    _Pragma("unroll") for (int b_ = 0; b_ < 4; b_++) { \
        acc[a_][b_][0]=0.f; acc[a_][b_][1]=0.f; acc[a_][b_][2]=0.f; acc[a_][b_][3]=0.f; }

#define GEMM_MAINLOOP(Aptr, ldA, Bptr, ldB, bn0, NIT) do { \
    float4 vr[4]; \
    ldgA(Aptr, ldA, row0, 0, tid, vr); \
    cpB(aB[0], Bptr, ldB, bn0, 0, tid); \
    CP_COMMIT(); \
    stsA(aA[0], tid, vr); \
    CP_WAIT0(); \
    __syncthreads(); \
    int buf = 0; \
    for (int it = 0; it < (NIT); it++) { \
        bool pf = (it + 1 < (NIT)); \
        if (pf) { \
            ldgA(Aptr, ldA, row0, (it + 1) * 32, tid, vr); \
            cpB(aB[buf ^ 1], Bptr, ldB, bn0, (it + 1) * 32, tid); \
            CP_COMMIT(); \
        } \
        mm_compute(aA[buf], aB[buf], lane, wm, wn, acc); \
        if (pf) stsA(aA[buf ^ 1], tid, vr); \
        CP_WAIT0(); \
        __syncthreads(); \
        buf ^= 1; \
    } } while (0)

// ---------------------------------------------------------------------------
// GEMM1: h = LayerNorm(x @ W1 + b1)
// ---------------------------------------------------------------------------
__global__ __launch_bounds__(256) void k1_mma(
    const float* __restrict__ x, const float* __restrict__ b1,
    const float* __restrict__ ln_g, const float* __restrict__ ln_b)
{
    extern __shared__ char smraw[];
    SmemG* s = (SmemG*)smraw;
    int tid = threadIdx.x;
    int lane = tid & 31, wid = tid >> 5;
    int row0 = blockIdx.x * 128;
    int wm = (wid >> 2) * 64, wn = (wid & 3) * 32;

    if (tid < 128) {
        s->parb[tid]  = b1[tid];
        s->parg[tid]  = ln_g[tid];
        s->parbt[tid] = ln_b[tid];
    }
    uint32_t aA[2], aB[2];
    aA[0] = smem_u32(&s->u.mm.A[0][0]); aA[1] = smem_u32(&s->u.mm.A[1][0]);
    aB[0] = smem_u32(&s->u.mm.B[0][0]); aB[1] = smem_u32(&s->u.mm.B[1][0]);

    float acc[4][4][4];
    ACC_INIT(acc);
    GEMM_MAINLOOP(x, ND, g_W1r, NH, 0, ND / 32);

    int tr = lane >> 2, tc = lane & 3;
    float* epi = s->u.epi;
#pragma unroll
    for (int mt = 0; mt < 4; mt++) {
#pragma unroll
        for (int nt = 0; nt < 4; nt++) {
            int row = wm + mt * 16 + tr;
            int col = wn + nt * 8 + 2 * tc;
            float bb0 = s->parb[col], bb1 = s->parb[col + 1];
            epi[row * LDE_S + col]           = acc[mt][nt][0] + bb0;
            epi[row * LDE_S + col + 1]       = acc[mt][nt][1] + bb1;
            epi[(row + 8) * LDE_S + col]     = acc[mt][nt][2] + bb0;
            epi[(row + 8) * LDE_S + col + 1] = acc[mt][nt][3] + bb1;
        }
    }
    __syncthreads();

    for (int r = wid; r < 128; r += 8) {
        float x0 = epi[r * LDE_S + lane];
        float x1 = epi[r * LDE_S + lane + 32];
        float x2 = epi[r * LDE_S + lane + 64];
        float x3 = epi[r * LDE_S + lane + 96];
        float su = x0 + x1 + x2 + x3;
        float sq = x0 * x0 + x1 * x1 + x2 * x2 + x3 * x3;
#pragma unroll
        for (int o = 16; o; o >>= 1) {
            su += __shfl_xor_sync(0xffffffffu, su, o);
            sq += __shfl_xor_sync(0xffffffffu, sq, o);
        }
        float mean = su * (1.f / 128.f);
        float var  = sq * (1.f / 128.f) - mean * mean;
        if (lane == 0) {
            s->mean[r] = mean;
            s->rstd[r] = rsqrtf(fmaxf(var, 0.f) + 1e-5f);
        }
    }
    __syncthreads();

#pragma unroll
    for (int q = 0; q < 16; q++) {
        int idx = tid + 256 * q;
        int r = idx >> 5, c4 = idx & 31;
        int row = row0 + r;
        if (row < NM) {
            float4 v = *(float4*)&epi[r * LDE_S + 4 * c4];
            float mean = s->mean[r], rstd = s->rstd[r];
            float4 gv = *(float4*)&s->parg[4 * c4];
            float4 bv = *(float4*)&s->parbt[4 * c4];
            float4 o;
            o.x = (v.x - mean) * rstd * gv.x + bv.x;
            o.y = (v.y - mean) * rstd * gv.y + bv.y;
            o.z = (v.z - mean) * rstd * gv.z + bv.z;
            o.w = (v.w - mean) * rstd * gv.w + bv.w;
            *(float4*)(g_h + (size_t)row * NH + 4 * c4) = o;
        }
    }
}

// ---------------------------------------------------------------------------
// k_gate: per-batch gate + LN -> g_hg, g_hn
// ---------------------------------------------------------------------------
struct SmemGate {
    float h[NT][128];
    float rowm[32];
    float gate[32];
};
__global__ __launch_bounds__(256) void k_gate(
    const float* __restrict__ T_W, const float* __restrict__ T_b,
    const float* __restrict__ n_g, const float* __restrict__ n_b)
{
    __shared__ SmemGate s;
    int tid = threadIdx.x;
    int lane = tid & 31, wid = tid >> 5;
    int b = blockIdx.x;
    const float* hg = g_h + (size_t)b * NT * NH;

    for (int idx = tid; idx < NT * NH / 4; idx += 256)
        ((float4*)&s.h[0][0])[idx] = ((const float4*)hg)[idx];
    __syncthreads();

    for (int r = wid; r < NT; r += 8) {
        float a = s.h[r][lane] + s.h[r][lane + 32] + s.h[r][lane + 64] + s.h[r][lane + 96];
#pragma unroll
        for (int o = 16; o; o >>= 1) a += __shfl_xor_sync(0xffffffffu, a, o);
        if (lane == 0) s.rowm[r] = a * (1.f / 128.f);
    }
    __syncthreads();

    if (wid == 0) {
        float val = -1e30f;
        if (lane < NT) {
            float a = T_b[lane];
#pragma unroll
            for (int u = 0; u < NT; u++) a += s.rowm[u] * T_W[u * NT + lane];
            val = a;
        }
        float m = val;
#pragma unroll
        for (int o = 16; o; o >>= 1) m = fmaxf(m, __shfl_xor_sync(0xffffffffu, m, o));
        float e = (lane < NT) ? expf(val - m) : 0.f;
        float se = e;
#pragma unroll
        for (int o = 16; o; o >>= 1) se += __shfl_xor_sync(0xffffffffu, se, o);
        if (lane < NT) s.gate[lane] = e / se;
    }
    __syncthreads();

    for (int idx = tid; idx < NT * NH; idx += 256) {
        int r = idx >> 7;
        float v = ((float*)s.h)[idx] * s.gate[r];
        ((float*)s.h)[idx] = v;
    }
    __syncthreads();
    float* hgo = g_hg + (size_t)b * NT * NH;
    for (int idx = tid; idx < NT * NH / 4; idx += 256)
        ((float4*)hgo)[idx] = ((const float4*)&s.h[0][0])[idx];

    float* hno = g_hn + (size_t)b * NT * NH;
    {
        float ng0 = n_g[lane], ng1 = n_g[lane + 32], ng2 = n_g[lane + 64], ng3 = n_g[lane + 96];
        float nb0 = n_b[lane], nb1 = n_b[lane + 32], nb2 = n_b[lane + 64], nb3 = n_b[lane + 96];
        for (int r = wid; r < NT; r += 8) {
            float x0 = s.h[r][lane],      x1 = s.h[r][lane + 32];
            float x2 = s.h[r][lane + 64], x3 = s.h[r][lane + 96];
            float su = x0 + x1 + x2 + x3;
            float sq = x0 * x0 + x1 * x1 + x2 * x2 + x3 * x3;
#pragma unroll
            for (int o = 16; o; o >>= 1) {
                su += __shfl_xor_sync(0xffffffffu, su, o);
                sq += __shfl_xor_sync(0xffffffffu, sq, o);
            }
            float mean = su * (1.f / 128.f);
            float rstd = rsqrtf(sq * (1.f / 128.f) - mean * mean + 1e-5f);
            hno[r * NH + lane]      = (x0 - mean) * rstd * ng0 + nb0;
            hno[r * NH + lane + 32] = (x1 - mean) * rstd * ng1 + nb1;
            hno[r * NH + lane + 64] = (x2 - mean) * rstd * ng2 + nb2;
            hno[r * NH + lane + 96] = (x3 - mean) * rstd * ng3 + nb3;
        }
    }
}

// ---------------------------------------------------------------------------
// k_qkv: g_qkv = g_hn @ [Wq|Wk|Wv] + b    grid (370, 3)
// ---------------------------------------------------------------------------
__global__ __launch_bounds__(256) void k_qkv()
{
    extern __shared__ char smraw[];
    SmemG* s = (SmemG*)smraw;
    int tid = threadIdx.x;
    int lane = tid & 31, wid = tid >> 5;
    int row0 = blockIdx.x * 128;
    int n0   = blockIdx.y * 128;
    int wm = (wid >> 2) * 64, wn = (wid & 3) * 32;

    if (tid < 128) s->parb[tid] = g_bqkv[n0 + tid];
    uint32_t aA[2], aB[2];
    aA[0] = smem_u32(&s->u.mm.A[0][0]); aA[1] = smem_u32(&s->u.mm.A[1][0]);
    aB[0] = smem_u32(&s->u.mm.B[0][0]); aB[1] = smem_u32(&s->u.mm.B[1][0]);

    float acc[4][4][4];
    ACC_INIT(acc);
    GEMM_MAINLOOP(g_hn, NH, g_Wqkvr, 384, n0, NH / 32);

    int tr = lane >> 2, tc = lane & 3;
#pragma unroll
    for (int mt = 0; mt < 4; mt++) {
#pragma unroll
        for (int nt = 0; nt < 4; nt++) {
            int colL = wn + nt * 8 + 2 * tc;
            float bb0 = s->parb[colL], bb1 = s->parb[colL + 1];
            int row = row0 + wm + mt * 16 + tr;
            if (row < NM)
                *(float2*)(g_qkv + (size_t)row * 384 + n0 + colL) =
                    make_float2(acc[mt][nt][0] + bb0, acc[mt][nt][1] + bb1);
            if (row + 8 < NM)
                *(float2*)(g_qkv + (size_t)(row + 8) * 384 + n0 + colL) =
                    make_float2(acc[mt][nt][2] + bb0, acc[mt][nt][3] + bb1);
        }
    }
}

// ---------------------------------------------------------------------------
// k_att: per-batch scores + softmax + attn@v -> g_o
// ---------------------------------------------------------------------------
struct SmemA {
    float q[NT][128];
    float kT[128][33];
    float v[NT][128];
    float sc[NT][32];
};
__global__ __launch_bounds__(256) void k_att()
{
    extern __shared__ char smraw[];
    SmemA* s = (SmemA*)smraw;
    int tid = threadIdx.x;
    int lane = tid & 31, wid = tid >> 5;
    int b = blockIdx.x;
    const float* qkv = g_qkv + (size_t)b * NT * 384;

    // load q/k/v; k transposed
    for (int idx = tid; idx < NT * 96; idx += 256) {
        int r = idx / 96, c4 = idx - (idx / 96) * 96;
        float4 t = *(const float4*)(qkv + (size_t)r * 384 + 4 * c4);
        if (c4 < 32) {
            *(float4*)&s->q[r][4 * c4] = t;
        } else if (c4 < 64) {
            int kc = 4 * (c4 - 32);
            s->kT[kc + 0][r] = t.x;
            s->kT[kc + 1][r] = t.y;
            s->kT[kc + 2][r] = t.z;
            s->kT[kc + 3][r] = t.w;
        } else {
            *(float4*)&s->v[r][4 * (c4 - 64)] = t;
        }
    }
    __syncthreads();

    const float SCALE = 0.08838834764831845f;  // sqrt(1/128)
    for (int t = wid; t < NT; t += 8) {
        float a = 0.f;
#pragma unroll 16
        for (int j = 0; j < 128; j++)
            a += s->q[t][j] * s->kT[j][lane];
        float val = (lane < NT) ? a * SCALE : -1e30f;
        float m = val;
#pragma unroll
        for (int o = 16; o; o >>= 1) m = fmaxf(m, __shfl_xor_sync(0xffffffffu, m, o));
        float e = (lane < NT) ? expf(val - m) : 0.f;
        float se = e;
#pragma unroll
        for (int o = 16; o; o >>= 1) se += __shfl_xor_sync(0xffffffffu, se, o);
        s->sc[t][lane] = e / se;
    }
    __syncthreads();

    {
        int col = tid & 127, rp = tid >> 7;
        float* ob = g_o + (size_t)b * NT * NH;
#pragma unroll
        for (int j = 0; j < 15; j++) {
            int r = rp + 2 * j;
            if (r < NT) {
                float a = 0.f;
#pragma unroll
                for (int u = 0; u < NT; u++) a += s->sc[r][u] * s->v[u][col];
                ob[r * NH + col] = a;
            }
        }
    }
}

// ---------------------------------------------------------------------------
// k_oproj: g_h = g_o @ Wo + bo + g_hg     grid (370)
// ---------------------------------------------------------------------------
__global__ __launch_bounds__(256) void k_oproj(const float* __restrict__ bo)
{
    extern __shared__ char smraw[];
    SmemG* s = (SmemG*)smraw;
    int tid = threadIdx.x;
    int lane = tid & 31, wid = tid >> 5;
    int row0 = blockIdx.x * 128;
    int wm = (wid >> 2) * 64, wn = (wid & 3) * 32;

    if (tid < 128) s->parb[tid] = bo[tid];
    uint32_t aA[2], aB[2];
    aA[0] = smem_u32(&s->u.mm.A[0][0]); aA[1] = smem_u32(&s->u.mm.A[1][0]);
    aB[0] = smem_u32(&s->u.mm.B[0][0]); aB[1] = smem_u32(&s->u.mm.B[1][0]);

    float acc[4][4][4];
    ACC_INIT(acc);
    GEMM_MAINLOOP(g_o, NH, g_Wor, NH, 0, NH / 32);

    int tr = lane >> 2, tc = lane & 3;
#pragma unroll
    for (int mt = 0; mt < 4; mt++) {
#pragma unroll
        for (int nt = 0; nt < 4; nt++) {
            int colL = wn + nt * 8 + 2 * tc;
            float bb0 = s->parb[colL], bb1 = s->parb[colL + 1];
            int row = row0 + wm + mt * 16 + tr;
            if (row < NM) {
                float2 rres = *(const float2*)(g_hg + (size_t)row * NH + colL);
                *(float2*)(g_h + (size_t)row * NH + colL) =
                    make_float2(acc[mt][nt][0] + bb0 + rres.x, acc[mt][nt][1] + bb1 + rres.y);
            }
            if (row + 8 < NM) {
                float2 rres = *(const float2*)(g_hg + (size_t)(row + 8) * NH + colL);
                *(float2*)(g_h + (size_t)(row + 8) * NH + colL) =
                    make_float2(acc[mt][nt][2] + bb0 + rres.x, acc[mt][nt][3] + bb1 + rres.y);
            }
        }
    }
}

// ---------------------------------------------------------------------------
// GEMM2: out = h @ W2 + b2     grid (370, 8)
// ---------------------------------------------------------------------------
__global__ __launch_bounds__(256) void k2_mma(
    const float* __restrict__ b2, float* __restrict__ out)
{
    extern __shared__ char smraw[];
    SmemG* s = (SmemG*)smraw;
    int tid = threadIdx.x;
    int lane = tid & 31, wid = tid >> 5;
    int row0 = blockIdx.x * 128;
    int n0   = blockIdx.y * 128;
    int wm = (wid >> 2) * 64, wn = (wid & 3) * 32;

    if (tid < 128) s->parb[tid] = b2[n0 + tid];
    uint32_t aA[2], aB[2];
    aA[0] = smem_u32(&s->u.mm.A[0][0]); aA[1] = smem_u32(&s->u.mm.A[1][0]);
    aB[0] = smem_u32(&s->u.mm.B[0][0]); aB[1] = smem_u32(&s->u.mm.B[1][0]);

    float acc[4][4][4];
    ACC_INIT(acc);
    GEMM_MAINLOOP(g_h, NH, g_W2r, ND, n0, NH / 32);

    int tr = lane >> 2, tc = lane & 3;
#pragma unroll
    for (int mt = 0; mt < 4; mt++) {
#pragma unroll
        for (int nt = 0; nt < 4; nt++) {
            int colL = wn + nt * 8 + 2 * tc;
            int col  = n0 + colL;
            float bb0 = s->parb[colL], bb1 = s->parb[colL + 1];
            int row = row0 + wm + mt * 16 + tr;
            if (row < NM)
                *(float2*)(out + (size_t)row * ND + col) =
                    make_float2(acc[mt][nt][0] + bb0, acc[mt][nt][1] + bb1);
            if (row + 8 < NM)
                *(float2*)(out + (size_t)(row + 8) * ND + col) =
                    make_float2(acc[mt][nt][2] + bb0, acc[mt][nt][3] + bb1);
        }
    }
}

// ---------------------------------------------------------------------------
extern "C" void kernel_launch(void* const* d_in, const int* in_sizes, int n_in,
                              void* d_out, int out_size)
{
    const float* x    = (const float*)d_in[0];
    const float* W1   = (const float*)d_in[1];
    const float* b1   = (const float*)d_in[2];
    const float* ln_g = (const float*)d_in[3];
    const float* ln_b = (const float*)d_in[4];
    const float* T_W  = (const float*)d_in[5];
    const float* T_b  = (const float*)d_in[6];
    const float* Wq   = (const float*)d_in[7];
    const float* bq   = (const float*)d_in[8];
    const float* Wk   = (const float*)d_in[9];
    const float* bk   = (const float*)d_in[10];
    const float* Wv   = (const float*)d_in[11];
    const float* bv   = (const float*)d_in[12];
    const float* Wo   = (const float*)d_in[13];
    const float* bo   = (const float*)d_in[14];
    const float* n_g  = (const float*)d_in[15];
    const float* n_b  = (const float*)d_in[16];
    const float* W2   = (const float*)d_in[17];
    const float* b2   = (const float*)d_in[18];
    float* out = (float*)d_out;

    int dynG = (int)sizeof(SmemG);
    int dynA = (int)sizeof(SmemA);
    cudaFuncSetAttribute(k1_mma,  cudaFuncAttributeMaxDynamicSharedMemorySize, dynG);
    cudaFuncSetAttribute(k_qkv,   cudaFuncAttributeMaxDynamicSharedMemorySize, dynG);
    cudaFuncSetAttribute(k_att,   cudaFuncAttributeMaxDynamicSharedMemorySize, dynA);
    cudaFuncSetAttribute(k_oproj, cudaFuncAttributeMaxDynamicSharedMemorySize, dynG);
    cudaFuncSetAttribute(k2_mma,  cudaFuncAttributeMaxDynamicSharedMemorySize, dynG);

    float* w1r; cudaGetSymbolAddress((void**)&w1r, g_W1r);
    float* w2r; cudaGetSymbolAddress((void**)&w2r, g_W2r);
    float* wor; cudaGetSymbolAddress((void**)&wor, g_Wor);

    k_round<<<(ND * NH + 255) / 256, 256>>>(W1, w1r, ND * NH);
    k_round<<<(NH * ND + 255) / 256, 256>>>(W2, w2r, NH * ND);
    k_round<<<(NH * NH + 255) / 256, 256>>>(Wo, wor, NH * NH);
    k_pack_qkv<<<(3 * NH * NH + 255) / 256, 256>>>(Wq, Wk, Wv, bq, bk, bv);

    int gm = (NM + 127) / 128;  // 370
    k1_mma<<<gm, 256, dynG>>>(x, b1, ln_g, ln_b);
    k_gate<<<NB, 256>>>(T_W, T_b, n_g, n_b);
    k_qkv<<<dim3(gm, 3), 256, dynG>>>();
    k_att<<<NB, 256, dynA>>>();
    k_oproj<<<gm, 256, dynG>>>(bo);
    k2_mma<<<dim3(gm, ND / 128), 256, dynG>>>(b2, out);
}

// round 11
// speedup vs baseline: 2.8664x; 1.0690x over previous
#include <cuda_runtime.h>
#include <math.h>
#include <stdint.h>

#define NB 1576
#define NT 30
#define ND 1024
#define NH 128
#define NM (NB*NT)   // 47280

// scratch
__device__ float g_h  [(size_t)NM * NH];   // LN(x@W1+b1)
__device__ float g_hg [(size_t)NM * NH];   // gated h (residual)
__device__ float g_o  [(size_t)NM * NH];   // attn @ v
__device__ float g_qkv[(size_t)NM * 384];  // q|k|v
__device__ float g_W1r[(size_t)ND * NH];
__device__ float g_W2r[(size_t)NH * ND];
__device__ float g_Wor[(size_t)NH * NH];
__device__ float g_Wqkvr[(size_t)NH * 384];
__device__ float g_bqkv[384];

// ---------------------------------------------------------------------------
// helpers
// ---------------------------------------------------------------------------
__device__ __forceinline__ uint32_t smem_u32(const void* p) {
    uint32_t a;
    asm("{ .reg .u64 t; cvta.to.shared.u64 t, %1; cvt.u32.u64 %0, t; }" : "=r"(a) : "l"(p));
    return a;
}
__device__ __forceinline__ uint32_t f2tf32(float f) {
    uint32_t r; asm("cvt.rna.tf32.f32 %0, %1;" : "=r"(r) : "f"(f)); return r;
}
__device__ __forceinline__ float f2tf32f(float f) { return __uint_as_float(f2tf32(f)); }
__device__ __forceinline__ void sts128(uint32_t a, uint32_t x, uint32_t y, uint32_t z, uint32_t w) {
    asm volatile("st.shared.v4.b32 [%0], {%1,%2,%3,%4};" :: "r"(a), "r"(x), "r"(y), "r"(z), "r"(w));
}
__device__ __forceinline__ uint32_t lds_u(uint32_t a) {
    uint32_t v; asm volatile("ld.shared.b32 %0, [%1];" : "=r"(v) : "r"(a)); return v;
}
__device__ __forceinline__ void cp16(uint32_t dst, const void* src) {
    asm volatile("cp.async.cg.shared.global [%0], [%1], 16;" :: "r"(dst), "l"(src));
}
#define CP_COMMIT() asm volatile("cp.async.commit_group;" ::: "memory")
#define CP_WAIT0()  asm volatile("cp.async.wait_group 0;" ::: "memory")

// ---------------------------------------------------------------------------
// layouts
// ---------------------------------------------------------------------------
#define LDA_S 36
#define LDB_S 136
#define LDE_S 132
#define LDH   132
struct SmemG {
    union {
        struct {
            float A[2][128 * LDA_S];
            float B[2][32 * LDB_S];
        } mm;
        float epi[128 * LDE_S];
    } u;
    float parb[128];
    float parg[128];
    float parbt[128];
    float mean[128];
    float rstd[128];
};
struct SmemQ {                      // gate+qkv fused kernel
    float hn[128 * LDH];            // LN output (tf32-rounded), rows 120..127 zero
    float Bb[2][32 * LDB_S];
    float rowm[120];
    float gate[120];
    float parb[384];
};
struct SmemO {                      // oproj+gemm2 fused kernel
    union {
        float hbuf[128 * LDH];      // phase-2 A (tf32-rounded)
        float Amm[2][128 * LDA_S];  // phase-1 A buffers (fits: 9216 < 16896 floats)
    } a;
    float Bb[2][32 * LDB_S];
    float parb[128];                // bo
};

// ---------------------------------------------------------------------------
// fused prep: tf32-round W1/W2/Wo, pack+round Wqkv, pack bqkv
// ---------------------------------------------------------------------------
__global__ void k_prep(const float* __restrict__ W1, const float* __restrict__ W2,
                       const float* __restrict__ Wo,
                       const float* __restrict__ Wq, const float* __restrict__ Wk,
                       const float* __restrict__ Wv,
                       const float* __restrict__ bq, const float* __restrict__ bk,
                       const float* __restrict__ bv) {
    int i = blockIdx.x * 256 + threadIdx.x;
    const int N1 = ND * NH, N2 = NH * ND, N3 = NH * NH, N4 = 3 * NH * NH;
    if (i < N1) {
        g_W1r[i] = f2tf32f(W1[i]);
    } else if (i < N1 + N2) {
        int j = i - N1;
        g_W2r[j] = f2tf32f(W2[j]);
    } else if (i < N1 + N2 + N3) {
        int j = i - N1 - N2;
        g_Wor[j] = f2tf32f(Wo[j]);
    } else if (i < N1 + N2 + N3 + N4) {
        int j = i - N1 - N2 - N3;
        int m = j / (NH * NH);
        int r = (j / NH) % NH;
        int n = j % NH;
        const float* W = (m == 0) ? Wq : (m == 1) ? Wk : Wv;
        g_Wqkvr[(size_t)r * 384 + m * NH + n] = f2tf32f(W[(size_t)r * NH + n]);
    } else if (i < N1 + N2 + N3 + N4 + 384) {
        int j = i - N1 - N2 - N3 - N4;
        int m = j / NH, n = j % NH;
        const float* bb = (m == 0) ? bq : (m == 1) ? bk : bv;
        g_bqkv[j] = bb[n];
    }
}

// ---------------------------------------------------------------------------
// mainloop building blocks
// ---------------------------------------------------------------------------
__device__ __forceinline__ void ldgA(const float* __restrict__ Ag, int ldA,
                                     int row0, int k0, int tid, float4 v[4]) {
#pragma unroll
    for (int q = 0; q < 4; q++) {
        int idx = tid + 256 * q;
        int r = idx >> 3, j = idx & 7;
        int row = row0 + r;
        float4 t = make_float4(0.f, 0.f, 0.f, 0.f);
        if (row < NM) t = *(const float4*)(Ag + (size_t)row * ldA + k0 + j * 4);
        v[q] = t;
    }
}
__device__ __forceinline__ void stsA(uint32_t As, int tid, const float4 v[4]) {
#pragma unroll
    for (int q = 0; q < 4; q++) {
        int idx = tid + 256 * q;
        int r = idx >> 3, j = idx & 7;
        sts128(As + (r * LDA_S + j * 4) * 4,
               f2tf32(v[q].x), f2tf32(v[q].y), f2tf32(v[q].z), f2tf32(v[q].w));
    }
}
__device__ __forceinline__ void cpB(uint32_t Bs, const float* __restrict__ Bg,
                                    int ldB, int bn0, int k0, int tid) {
#pragma unroll
    for (int q = 0; q < 4; q++) {
        int idx = tid + 256 * q;
        int kk = idx >> 5, jc = idx & 31;
        cp16(Bs + (kk * LDB_S + jc * 4) * 4,
             Bg + (size_t)(k0 + kk) * ldB + bn0 + jc * 4);
    }
}

// A in LDA_S-stride staging buffer (K-chunk local)
__device__ __forceinline__ void mm_compute(uint32_t As, uint32_t Bs,
                                           int lane, int wm, int wn,
                                           float acc[4][4][4]) {
    int tr = lane >> 2, tc = lane & 3;
#pragma unroll
    for (int ks = 0; ks < 4; ks++) {
        int k0 = ks * 8;
        uint32_t af[4][4];
#pragma unroll
        for (int mt = 0; mt < 4; mt++) {
            int row = wm + mt * 16 + tr;
            uint32_t b0 = As + (row * LDA_S + k0 + tc) * 4;
            af[mt][0] = lds_u(b0);
            af[mt][1] = lds_u(b0 + 8 * LDA_S * 4);
            af[mt][2] = lds_u(b0 + 16);
            af[mt][3] = lds_u(b0 + 8 * LDA_S * 4 + 16);
        }
        uint32_t bf[4][2];
#pragma unroll
        for (int nt = 0; nt < 4; nt++) {
            int col = wn + nt * 8 + tr;
            uint32_t b0 = Bs + ((k0 + tc) * LDB_S + col) * 4;
            bf[nt][0] = lds_u(b0);
            bf[nt][1] = lds_u(b0 + 4 * LDB_S * 4);
        }
#pragma unroll
        for (int mt = 0; mt < 4; mt++)
#pragma unroll
            for (int nt = 0; nt < 4; nt++)
                asm volatile(
                    "mma.sync.aligned.m16n8k8.row.col.f32.tf32.tf32.f32 "
                    "{%0,%1,%2,%3}, {%4,%5,%6,%7}, {%8,%9}, {%0,%1,%2,%3};"
                    : "+f"(acc[mt][nt][0]), "+f"(acc[mt][nt][1]),
                      "+f"(acc[mt][nt][2]), "+f"(acc[mt][nt][3])
                    : "r"(af[mt][0]), "r"(af[mt][1]), "r"(af[mt][2]), "r"(af[mt][3]),
                      "r"(bf[nt][0]), "r"(bf[nt][1]));
    }
}

// A resident in LDH-stride full-K smem buffer (kbase selects K chunk)
__device__ __forceinline__ void mm_computeA(uint32_t Ab, uint32_t Bs, int kbase,
                                            int lane, int wm, int wn,
                                            float acc[4][4][4]) {
    int tr = lane >> 2, tc = lane & 3;
#pragma unroll
    for (int ks = 0; ks < 4; ks++) {
        int ka = kbase + ks * 8;
        int kb = ks * 8;
        uint32_t af[4][4];
#pragma unroll
        for (int mt = 0; mt < 4; mt++) {
            int row = wm + mt * 16 + tr;
            uint32_t b0 = Ab + (row * LDH + ka + tc) * 4;
            af[mt][0] = lds_u(b0);
            af[mt][1] = lds_u(b0 + 8 * LDH * 4);
            af[mt][2] = lds_u(b0 + 16);
            af[mt][3] = lds_u(b0 + 8 * LDH * 4 + 16);
        }
        uint32_t bf[4][2];
#pragma unroll
        for (int nt = 0; nt < 4; nt++) {
            int col = wn + nt * 8 + tr;
            uint32_t b0 = Bs + ((kb + tc) * LDB_S + col) * 4;
            bf[nt][0] = lds_u(b0);
            bf[nt][1] = lds_u(b0 + 4 * LDB_S * 4);
        }
#pragma unroll
        for (int mt = 0; mt < 4; mt++)
#pragma unroll
            for (int nt = 0; nt < 4; nt++)
                asm volatile(
                    "mma.sync.aligned.m16n8k8.row.col.f32.tf32.tf32.f32 "
                    "{%0,%1,%2,%3}, {%4,%5,%6,%7}, {%8,%9}, {%0,%1,%2,%3};"
                    : "+f"(acc[mt][nt][0]), "+f"(acc[mt][nt][1]),
                      "+f"(acc[mt][nt][2]), "+f"(acc[mt][nt][3])
                    : "r"(af[mt][0]), "r"(af[mt][1]), "r"(af[mt][2]), "r"(af[mt][3]),
                      "r"(bf[nt][0]), "r"(bf[nt][1]));
    }
}

#define ACC_INIT(acc) \
    _Pragma("unroll") for (int a_ = 0; a_ < 4; a_++) \
    _Pragma("unroll") for (int b_ = 0; b_ < 4; b_++) { \
        acc[a_][b_][0]=0.f; acc[a_][b_][1]=0.f; acc[a_][b_][2]=0.f; acc[a_][b_][3]=0.f; }

#define GEMM_MAINLOOP(Aptr, ldA, Bptr, ldB, bn0, NIT) do { \
    float4 vr[4]; \
    ldgA(Aptr, ldA, row0, 0, tid, vr); \
    cpB(aB[0], Bptr, ldB, bn0, 0, tid); \
    CP_COMMIT(); \
    stsA(aA[0], tid, vr); \
    CP_WAIT0(); \
    __syncthreads(); \
    int buf = 0; \
    for (int it = 0; it < (NIT); it++) { \
        bool pf = (it + 1 < (NIT)); \
        if (pf) { \
            ldgA(Aptr, ldA, row0, (it + 1) * 32, tid, vr); \
            cpB(aB[buf ^ 1], Bptr, ldB, bn0, (it + 1) * 32, tid); \
            CP_COMMIT(); \
        } \
        mm_compute(aA[buf], aB[buf], lane, wm, wn, acc); \
        if (pf) stsA(aA[buf ^ 1], tid, vr); \
        CP_WAIT0(); \
        __syncthreads(); \
        buf ^= 1; \
    } } while (0)

// ---------------------------------------------------------------------------
// GEMM1: h = LayerNorm(x @ W1 + b1)
// ---------------------------------------------------------------------------
__global__ __launch_bounds__(256) void k1_mma(
    const float* __restrict__ x, const float* __restrict__ b1,
    const float* __restrict__ ln_g, const float* __restrict__ ln_b)
{
    extern __shared__ char smraw[];
    SmemG* s = (SmemG*)smraw;
    int tid = threadIdx.x;
    int lane = tid & 31, wid = tid >> 5;
    int row0 = blockIdx.x * 128;
    int wm = (wid >> 2) * 64, wn = (wid & 3) * 32;

    if (tid < 128) {
        s->parb[tid]  = b1[tid];
        s->parg[tid]  = ln_g[tid];
        s->parbt[tid] = ln_b[tid];
    }
    uint32_t aA[2], aB[2];
    aA[0] = smem_u32(&s->u.mm.A[0][0]); aA[1] = smem_u32(&s->u.mm.A[1][0]);
    aB[0] = smem_u32(&s->u.mm.B[0][0]); aB[1] = smem_u32(&s->u.mm.B[1][0]);

    float acc[4][4][4];
    ACC_INIT(acc);
    GEMM_MAINLOOP(x, ND, g_W1r, NH, 0, ND / 32);

    int tr = lane >> 2, tc = lane & 3;
    float* epi = s->u.epi;
#pragma unroll
    for (int mt = 0; mt < 4; mt++) {
#pragma unroll
        for (int nt = 0; nt < 4; nt++) {
            int row = wm + mt * 16 + tr;
            int col = wn + nt * 8 + 2 * tc;
            float bb0 = s->parb[col], bb1 = s->parb[col + 1];
            epi[row * LDE_S + col]           = acc[mt][nt][0] + bb0;
            epi[row * LDE_S + col + 1]       = acc[mt][nt][1] + bb1;
            epi[(row + 8) * LDE_S + col]     = acc[mt][nt][2] + bb0;
            epi[(row + 8) * LDE_S + col + 1] = acc[mt][nt][3] + bb1;
        }
    }
    __syncthreads();

    for (int r = wid; r < 128; r += 8) {
        float x0 = epi[r * LDE_S + lane];
        float x1 = epi[r * LDE_S + lane + 32];
        float x2 = epi[r * LDE_S + lane + 64];
        float x3 = epi[r * LDE_S + lane + 96];
        float su = x0 + x1 + x2 + x3;
        float sq = x0 * x0 + x1 * x1 + x2 * x2 + x3 * x3;
#pragma unroll
        for (int o = 16; o; o >>= 1) {
            su += __shfl_xor_sync(0xffffffffu, su, o);
            sq += __shfl_xor_sync(0xffffffffu, sq, o);
        }
        float mean = su * (1.f / 128.f);
        float var  = sq * (1.f / 128.f) - mean * mean;
        if (lane == 0) {
            s->mean[r] = mean;
            s->rstd[r] = rsqrtf(fmaxf(var, 0.f) + 1e-5f);
        }
    }
    __syncthreads();

#pragma unroll
    for (int q = 0; q < 16; q++) {
        int idx = tid + 256 * q;
        int r = idx >> 5, c4 = idx & 31;
        int row = row0 + r;
        if (row < NM) {
            float4 v = *(float4*)&epi[r * LDE_S + 4 * c4];
            float mean = s->mean[r], rstd = s->rstd[r];
            float4 gv = *(float4*)&s->parg[4 * c4];
            float4 bv = *(float4*)&s->parbt[4 * c4];
            float4 o;
            o.x = (v.x - mean) * rstd * gv.x + bv.x;
            o.y = (v.y - mean) * rstd * gv.y + bv.y;
            o.z = (v.z - mean) * rstd * gv.z + bv.z;
            o.w = (v.w - mean) * rstd * gv.w + bv.w;
            *(float4*)(g_h + (size_t)row * NH + 4 * c4) = o;
        }
    }
}

// ---------------------------------------------------------------------------
// k_gateqkv: 4 batches (120 rows) per block. gate + LN in smem, then
// qkv GEMM with A resident in smem. grid = NB/4 = 394.
// ---------------------------------------------------------------------------
__global__ __launch_bounds__(256) void k_gateqkv(
    const float* __restrict__ T_W, const float* __restrict__ T_b,
    const float* __restrict__ n_g, const float* __restrict__ n_b)
{
    extern __shared__ char smraw[];
    SmemQ* s = (SmemQ*)smraw;
    int tid = threadIdx.x;
    int lane = tid & 31, wid = tid >> 5;
    int row0 = blockIdx.x * 4 * NT;   // 120 rows
    const float* hg = g_h + (size_t)row0 * NH;

    for (int i = tid; i < 384; i += 256) s->parb[i] = g_bqkv[i];

    // load h 120x128 into hn (stride LDH)
    for (int idx = tid; idx < 120 * 32; idx += 256) {
        int r = idx >> 5, c4 = idx & 31;
        float4 t = *(const float4*)(hg + (size_t)r * NH + 4 * c4);
        *(float4*)&s->hn[r * LDH + 4 * c4] = t;
    }
    // zero pad rows 120..127
    for (int idx = tid; idx < 8 * 32; idx += 256) {
        int r = 120 + (idx >> 5), c4 = idx & 31;
        *(float4*)&s->hn[r * LDH + 4 * c4] = make_float4(0.f, 0.f, 0.f, 0.f);
    }
    __syncthreads();

    // row means
    for (int r = wid; r < 120; r += 8) {
        float a = s->hn[r * LDH + lane] + s->hn[r * LDH + lane + 32]
                + s->hn[r * LDH + lane + 64] + s->hn[r * LDH + lane + 96];
#pragma unroll
        for (int o = 16; o; o >>= 1) a += __shfl_xor_sync(0xffffffffu, a, o);
        if (lane == 0) s->rowm[r] = a * (1.f / 128.f);
    }
    __syncthreads();

    // gate softmax per batch (warps 0-3)
    if (wid < 4) {
        int bi = wid;
        float val = -1e30f;
        if (lane < NT) {
            float a = T_b[lane];
#pragma unroll
            for (int u = 0; u < NT; u++) a += s->rowm[bi * NT + u] * T_W[u * NT + lane];
            val = a;
        }
        float m = val;
#pragma unroll
        for (int o = 16; o; o >>= 1) m = fmaxf(m, __shfl_xor_sync(0xffffffffu, m, o));
        float e = (lane < NT) ? expf(val - m) : 0.f;
        float se = e;
#pragma unroll
        for (int o = 16; o; o >>= 1) se += __shfl_xor_sync(0xffffffffu, se, o);
        if (lane < NT) s->gate[bi * NT + lane] = e / se;
    }
    __syncthreads();

    // scale by gate -> write g_hg; LN -> hn (tf32-rounded)
    float* hgo = g_hg + (size_t)row0 * NH;
    {
        float ng0 = n_g[lane], ng1 = n_g[lane + 32], ng2 = n_g[lane + 64], ng3 = n_g[lane + 96];
        float nb0 = n_b[lane], nb1 = n_b[lane + 32], nb2 = n_b[lane + 64], nb3 = n_b[lane + 96];
        for (int r = wid; r < 120; r += 8) {
            float gt = s->gate[r];
            float x0 = s->hn[r * LDH + lane]      * gt;
            float x1 = s->hn[r * LDH + lane + 32] * gt;
            float x2 = s->hn[r * LDH + lane + 64] * gt;
            float x3 = s->hn[r * LDH + lane + 96] * gt;
            hgo[r * NH + lane]      = x0;
            hgo[r * NH + lane + 32] = x1;
            hgo[r * NH + lane + 64] = x2;
            hgo[r * NH + lane + 96] = x3;
            float su = x0 + x1 + x2 + x3;
            float sq = x0 * x0 + x1 * x1 + x2 * x2 + x3 * x3;
#pragma unroll
            for (int o = 16; o; o >>= 1) {
                su += __shfl_xor_sync(0xffffffffu, su, o);
                sq += __shfl_xor_sync(0xffffffffu, sq, o);
            }
            float mean = su * (1.f / 128.f);
            float rstd = rsqrtf(sq * (1.f / 128.f) - mean * mean + 1e-5f);
            s->hn[r * LDH + lane]      = f2tf32f((x0 - mean) * rstd * ng0 + nb0);
            s->hn[r * LDH + lane + 32] = f2tf32f((x1 - mean) * rstd * ng1 + nb1);
            s->hn[r * LDH + lane + 64] = f2tf32f((x2 - mean) * rstd * ng2 + nb2);
            s->hn[r * LDH + lane + 96] = f2tf32f((x3 - mean) * rstd * ng3 + nb3);
        }
    }
    __syncthreads();

    // qkv GEMM: A = hn (resident), B = Wqkvr, 3 N-tiles of 128
    int wm = (wid >> 2) * 64, wn = (wid & 3) * 32;
    int tr = lane >> 2, tc = lane & 3;
    uint32_t hnb = smem_u32(&s->hn[0]);
    uint32_t aB[2] = { smem_u32(&s->Bb[0][0]), smem_u32(&s->Bb[1][0]) };

    for (int ntile = 0; ntile < 3; ntile++) {
        int n0 = ntile * 128;
        float acc[4][4][4];
        ACC_INIT(acc);
        cpB(aB[0], g_Wqkvr, 384, n0, 0, tid); CP_COMMIT(); CP_WAIT0(); __syncthreads();
        int buf = 0;
        for (int it = 0; it < 4; it++) {
            if (it < 3) { cpB(aB[buf ^ 1], g_Wqkvr, 384, n0, (it + 1) * 32, tid); CP_COMMIT(); }
            mm_computeA(hnb, aB[buf], it * 32, lane, wm, wn, acc);
            CP_WAIT0(); __syncthreads();
            buf ^= 1;
        }
#pragma unroll
        for (int mt = 0; mt < 4; mt++) {
#pragma unroll
            for (int nt = 0; nt < 4; nt++) {
                int colL = wn + nt * 8 + 2 * tc;
                int col  = n0 + colL;
                float bb0 = s->parb[col], bb1 = s->parb[col + 1];
                int row = wm + mt * 16 + tr;
                if (row < 120)
                    *(float2*)(g_qkv + (size_t)(row0 + row) * 384 + col) =
                        make_float2(acc[mt][nt][0] + bb0, acc[mt][nt][1] + bb1);
                if (row + 8 < 120)
                    *(float2*)(g_qkv + (size_t)(row0 + row + 8) * 384 + col) =
                        make_float2(acc[mt][nt][2] + bb0, acc[mt][nt][3] + bb1);
            }
        }
    }
}

// ---------------------------------------------------------------------------
// k_att: per-batch scores + softmax + attn@v -> g_o (unchanged)
// ---------------------------------------------------------------------------
struct SmemA {
    float q[NT][128];
    float kT[128][33];
    float v[NT][128];
    float sc[NT][32];
};
__global__ __launch_bounds__(256) void k_att()
{
    extern __shared__ char smraw[];
    SmemA* s = (SmemA*)smraw;
    int tid = threadIdx.x;
    int lane = tid & 31, wid = tid >> 5;
    int b = blockIdx.x;
    const float* qkv = g_qkv + (size_t)b * NT * 384;

    for (int idx = tid; idx < NT * 96; idx += 256) {
        int r = idx / 96, c4 = idx - (idx / 96) * 96;
        float4 t = *(const float4*)(qkv + (size_t)r * 384 + 4 * c4);
        if (c4 < 32) {
            *(float4*)&s->q[r][4 * c4] = t;
        } else if (c4 < 64) {
            int kc = 4 * (c4 - 32);
            s->kT[kc + 0][r] = t.x;
            s->kT[kc + 1][r] = t.y;
            s->kT[kc + 2][r] = t.z;
            s->kT[kc + 3][r] = t.w;
        } else {
            *(float4*)&s->v[r][4 * (c4 - 64)] = t;
        }
    }
    __syncthreads();

    const float SCALE = 0.08838834764831845f;  // sqrt(1/128)
    for (int t = wid; t < NT; t += 8) {
        float a = 0.f;
#pragma unroll 16
        for (int j = 0; j < 128; j++)
            a += s->q[t][j] * s->kT[j][lane];
        float val = (lane < NT) ? a * SCALE : -1e30f;
        float m = val;
#pragma unroll
        for (int o = 16; o; o >>= 1) m = fmaxf(m, __shfl_xor_sync(0xffffffffu, m, o));
        float e = (lane < NT) ? expf(val - m) : 0.f;
        float se = e;
#pragma unroll
        for (int o = 16; o; o >>= 1) se += __shfl_xor_sync(0xffffffffu, se, o);
        s->sc[t][lane] = e / se;
    }
    __syncthreads();

    {
        int col = tid & 127, rp = tid >> 7;
        float* ob = g_o + (size_t)b * NT * NH;
#pragma unroll
        for (int j = 0; j < 15; j++) {
            int r = rp + 2 * j;
            if (r < NT) {
                float a = 0.f;
#pragma unroll
                for (int u = 0; u < NT; u++) a += s->sc[r][u] * s->v[u][col];
                ob[r * NH + col] = a;
            }
        }
    }
}

// ---------------------------------------------------------------------------
// k_oproj2: phase1 h = g_o @ Wo + bo + g_hg (into smem, tf32-rounded);
//           phase2 out = h @ W2 + b2 over 8 N-tiles. grid = 370.
// ---------------------------------------------------------------------------
__global__ __launch_bounds__(256) void k_oproj2(
    const float* __restrict__ bo, const float* __restrict__ b2,
    float* __restrict__ out)
{
    extern __shared__ char smraw[];
    SmemO* s = (SmemO*)smraw;
    int tid = threadIdx.x;
    int lane = tid & 31, wid = tid >> 5;
    int row0 = blockIdx.x * 128;
    int wm = (wid >> 2) * 64, wn = (wid & 3) * 32;

    if (tid < 128) s->parb[tid] = bo[tid];
    uint32_t aA[2], aB[2];
    aA[0] = smem_u32(&s->a.Amm[0][0]); aA[1] = smem_u32(&s->a.Amm[1][0]);
    aB[0] = smem_u32(&s->Bb[0][0]);    aB[1] = smem_u32(&s->Bb[1][0]);

    // phase 1: oproj
    float acc[4][4][4];
    ACC_INIT(acc);
    GEMM_MAINLOOP(g_o, NH, g_Wor, NH, 0, NH / 32);

    int tr = lane >> 2, tc = lane & 3;
    // write h (rounded) into hbuf; zero rows beyond NM
#pragma unroll
    for (int mt = 0; mt < 4; mt++) {
#pragma unroll
        for (int nt = 0; nt < 4; nt++) {
            int colL = wn + nt * 8 + 2 * tc;
            float bb0 = s->parb[colL], bb1 = s->parb[colL + 1];
            int row = wm + mt * 16 + tr;
            {
                int grow = row0 + row;
                float v0 = 0.f, v1 = 0.f;
                if (grow < NM) {
                    float2 rres = *(const float2*)(g_hg + (size_t)grow * NH + colL);
                    v0 = acc[mt][nt][0] + bb0 + rres.x;
                    v1 = acc[mt][nt][1] + bb1 + rres.y;
                }
                s->a.hbuf[row * LDH + colL]     = f2tf32f(v0);
                s->a.hbuf[row * LDH + colL + 1] = f2tf32f(v1);
            }
            {
                int grow = row0 + row + 8;
                float v2 = 0.f, v3 = 0.f;
                if (grow < NM) {
                    float2 rres = *(const float2*)(g_hg + (size_t)grow * NH + colL);
                    v2 = acc[mt][nt][2] + bb0 + rres.x;
                    v3 = acc[mt][nt][3] + bb1 + rres.y;
                }
                s->a.hbuf[(row + 8) * LDH + colL]     = f2tf32f(v2);
                s->a.hbuf[(row + 8) * LDH + colL + 1] = f2tf32f(v3);
            }
        }
    }
    __syncthreads();

    // phase 2: GEMM2 over 8 N-tiles, A resident in hbuf
    uint32_t hb = smem_u32(&s->a.hbuf[0]);
    for (int ntile = 0; ntile < 8; ntile++) {
        int n0 = ntile * 128;
        ACC_INIT(acc);
        cpB(aB[0], g_W2r, ND, n0, 0, tid); CP_COMMIT(); CP_WAIT0(); __syncthreads();
        int buf = 0;
        for (int it = 0; it < 4; it++) {
            if (it < 3) { cpB(aB[buf ^ 1], g_W2r, ND, n0, (it + 1) * 32, tid); CP_COMMIT(); }
            mm_computeA(hb, aB[buf], it * 32, lane, wm, wn, acc);
            CP_WAIT0(); __syncthreads();
            buf ^= 1;
        }
#pragma unroll
        for (int mt = 0; mt < 4; mt++) {
#pragma unroll
            for (int nt = 0; nt < 4; nt++) {
                int colL = wn + nt * 8 + 2 * tc;
                int col  = n0 + colL;
                float bb0 = __ldg(b2 + col), bb1 = __ldg(b2 + col + 1);
                int row = row0 + wm + mt * 16 + tr;
                if (row < NM)
                    *(float2*)(out + (size_t)row * ND + col) =
                        make_float2(acc[mt][nt][0] + bb0, acc[mt][nt][1] + bb1);
                if (row + 8 < NM)
                    *(float2*)(out + (size_t)(row + 8) * ND + col) =
                        make_float2(acc[mt][nt][2] + bb0, acc[mt][nt][3] + bb1);
            }
        }
    }
}

// ---------------------------------------------------------------------------
extern "C" void kernel_launch(void* const* d_in, const int* in_sizes, int n_in,
                              void* d_out, int out_size)
{
    const float* x    = (const float*)d_in[0];
    const float* W1   = (const float*)d_in[1];
    const float* b1   = (const float*)d_in[2];
    const float* ln_g = (const float*)d_in[3];
    const float* ln_b = (const float*)d_in[4];
    const float* T_W  = (const float*)d_in[5];
    const float* T_b  = (const float*)d_in[6];
    const float* Wq   = (const float*)d_in[7];
    const float* bq   = (const float*)d_in[8];
    const float* Wk   = (const float*)d_in[9];
    const float* bk   = (const float*)d_in[10];
    const float* Wv   = (const float*)d_in[11];
    const float* bv   = (const float*)d_in[12];
    const float* Wo   = (const float*)d_in[13];
    const float* bo   = (const float*)d_in[14];
    const float* n_g  = (const float*)d_in[15];
    const float* n_b  = (const float*)d_in[16];
    const float* W2   = (const float*)d_in[17];
    const float* b2   = (const float*)d_in[18];
    float* out = (float*)d_out;

    int dynG = (int)sizeof(SmemG);
    int dynQ = (int)sizeof(SmemQ);
    int dynA = (int)sizeof(SmemA);
    int dynO = (int)sizeof(SmemO);
    cudaFuncSetAttribute(k1_mma,    cudaFuncAttributeMaxDynamicSharedMemorySize, dynG);
    cudaFuncSetAttribute(k_gateqkv, cudaFuncAttributeMaxDynamicSharedMemorySize, dynQ);
    cudaFuncSetAttribute(k_att,     cudaFuncAttributeMaxDynamicSharedMemorySize, dynA);
    cudaFuncSetAttribute(k_oproj2,  cudaFuncAttributeMaxDynamicSharedMemorySize, dynO);

    const int PREP_N = ND * NH + NH * ND + NH * NH + 3 * NH * NH + 384;
    k_prep<<<(PREP_N + 255) / 256, 256>>>(W1, W2, Wo, Wq, Wk, Wv, bq, bk, bv);

    int gm = (NM + 127) / 128;  // 370
    k1_mma<<<gm, 256, dynG>>>(x, b1, ln_g, ln_b);
    k_gateqkv<<<NB / 4, 256, dynQ>>>(T_W, T_b, n_g, n_b);
    k_att<<<NB, 256, dynA>>>();
    k_oproj2<<<gm, 256, dynO>>>(bo, b2, out);
}

// round 14
// speedup vs baseline: 2.9576x; 1.0318x over previous
#include <cuda_runtime.h>
#include <math.h>
#include <stdint.h>

#define NB 1576
#define NT 30
#define ND 1024
#define NH 128
#define NM (NB*NT)   // 47280

// scratch
__device__ float g_h  [(size_t)NM * NH];   // LN(x@W1+b1)
__device__ float g_hg [(size_t)NM * NH];   // gated h (residual)
__device__ float g_o  [(size_t)NM * NH];   // attn @ v
__device__ float g_qkv[(size_t)NM * 384];  // q|k|v
__device__ float g_W1r[(size_t)ND * NH];
__device__ float g_W2r[(size_t)NH * ND];
__device__ float g_Wor[(size_t)NH * NH];
__device__ float g_Wqkvr[(size_t)NH * 384];
__device__ float g_bqkv[384];

// ---------------------------------------------------------------------------
// helpers
// ---------------------------------------------------------------------------
__device__ __forceinline__ uint32_t smem_u32(const void* p) {
    uint32_t a;
    asm("{ .reg .u64 t; cvta.to.shared.u64 t, %1; cvt.u32.u64 %0, t; }" : "=r"(a) : "l"(p));
    return a;
}
__device__ __forceinline__ uint32_t f2tf32(float f) {
    uint32_t r; asm("cvt.rna.tf32.f32 %0, %1;" : "=r"(r) : "f"(f)); return r;
}
__device__ __forceinline__ float f2tf32f(float f) { return __uint_as_float(f2tf32(f)); }
__device__ __forceinline__ void sts128(uint32_t a, uint32_t x, uint32_t y, uint32_t z, uint32_t w) {
    asm volatile("st.shared.v4.b32 [%0], {%1,%2,%3,%4};" :: "r"(a), "r"(x), "r"(y), "r"(z), "r"(w));
}
__device__ __forceinline__ uint32_t lds_u(uint32_t a) {
    uint32_t v; asm volatile("ld.shared.b32 %0, [%1];" : "=r"(v) : "r"(a)); return v;
}
__device__ __forceinline__ void cp16(uint32_t dst, const void* src) {
    asm volatile("cp.async.cg.shared.global [%0], [%1], 16;" :: "r"(dst), "l"(src));
}
#define CP_COMMIT() asm volatile("cp.async.commit_group;" ::: "memory")
#define CP_WAIT0()  asm volatile("cp.async.wait_group 0;" ::: "memory")

// ---------------------------------------------------------------------------
// layouts
// ---------------------------------------------------------------------------
#define LDA_S 36
#define LDB_S 136
#define LDE_S 132
#define LDH   132
struct SmemG {
    union {
        struct {
            float A[2][128 * LDA_S];
            float B[2][32 * LDB_S];
        } mm;
        float epi[128 * LDE_S];
    } u;
    float parb[128];
    float parg[128];
    float parbt[128];
    float mean[128];
    float rstd[128];
};
struct SmemQ {
    float hn[128 * LDH];
    float Bb[2][32 * LDB_S];
    float rowm[120];
    float gate[120];
    float parb[384];
};
struct SmemO {
    union {
        float hbuf[128 * LDH];
        float Amm[2][128 * LDA_S];
    } a;
    float Bb[2][32 * LDB_S];
    float parb[128];
};

// ---------------------------------------------------------------------------
// fused prep
// ---------------------------------------------------------------------------
__global__ void k_prep(const float* __restrict__ W1, const float* __restrict__ W2,
                       const float* __restrict__ Wo,
                       const float* __restrict__ Wq, const float* __restrict__ Wk,
                       const float* __restrict__ Wv,
                       const float* __restrict__ bq, const float* __restrict__ bk,
                       const float* __restrict__ bv) {
    int i = blockIdx.x * 256 + threadIdx.x;
    const int N1 = ND * NH, N2 = NH * ND, N3 = NH * NH, N4 = 3 * NH * NH;
    if (i < N1) {
        g_W1r[i] = f2tf32f(W1[i]);
    } else if (i < N1 + N2) {
        int j = i - N1;
        g_W2r[j] = f2tf32f(W2[j]);
    } else if (i < N1 + N2 + N3) {
        int j = i - N1 - N2;
        g_Wor[j] = f2tf32f(Wo[j]);
    } else if (i < N1 + N2 + N3 + N4) {
        int j = i - N1 - N2 - N3;
        int m = j / (NH * NH);
        int r = (j / NH) % NH;
        int n = j % NH;
        const float* W = (m == 0) ? Wq : (m == 1) ? Wk : Wv;
        g_Wqkvr[(size_t)r * 384 + m * NH + n] = f2tf32f(W[(size_t)r * NH + n]);
    } else if (i < N1 + N2 + N3 + N4 + 384) {
        int j = i - N1 - N2 - N3 - N4;
        int m = j / NH, n = j % NH;
        const float* bb = (m == 0) ? bq : (m == 1) ? bk : bv;
        g_bqkv[j] = bb[n];
    }
}

// ---------------------------------------------------------------------------
// mainloop building blocks
// ---------------------------------------------------------------------------
__device__ __forceinline__ void ldgA(const float* __restrict__ Ag, int ldA,
                                     int row0, int k0, int tid, float4 v[4]) {
#pragma unroll
    for (int q = 0; q < 4; q++) {
        int idx = tid + 256 * q;
        int r = idx >> 3, j = idx & 7;
        int row = row0 + r;
        float4 t = make_float4(0.f, 0.f, 0.f, 0.f);
        if (row < NM) t = *(const float4*)(Ag + (size_t)row * ldA + k0 + j * 4);
        v[q] = t;
    }
}
__device__ __forceinline__ void stsA(uint32_t As, int tid, const float4 v[4]) {
#pragma unroll
    for (int q = 0; q < 4; q++) {
        int idx = tid + 256 * q;
        int r = idx >> 3, j = idx & 7;
        sts128(As + (r * LDA_S + j * 4) * 4,
               f2tf32(v[q].x), f2tf32(v[q].y), f2tf32(v[q].z), f2tf32(v[q].w));
    }
}
__device__ __forceinline__ void cpB(uint32_t Bs, const float* __restrict__ Bg,
                                    int ldB, int bn0, int k0, int tid) {
#pragma unroll
    for (int q = 0; q < 4; q++) {
        int idx = tid + 256 * q;
        int kk = idx >> 5, jc = idx & 31;
        cp16(Bs + (kk * LDB_S + jc * 4) * 4,
             Bg + (size_t)(k0 + kk) * ldB + bn0 + jc * 4);
    }
}

__device__ __forceinline__ void mm_compute(uint32_t As, uint32_t Bs,
                                           int lane, int wm, int wn,
                                           float acc[4][4][4]) {
    int tr = lane >> 2, tc = lane & 3;
#pragma unroll
    for (int ks = 0; ks < 4; ks++) {
        int k0 = ks * 8;
        uint32_t af[4][4];
#pragma unroll
        for (int mt = 0; mt < 4; mt++) {
            int row = wm + mt * 16 + tr;
            uint32_t b0 = As + (row * LDA_S + k0 + tc) * 4;
            af[mt][0] = lds_u(b0);
            af[mt][1] = lds_u(b0 + 8 * LDA_S * 4);
            af[mt][2] = lds_u(b0 + 16);
            af[mt][3] = lds_u(b0 + 8 * LDA_S * 4 + 16);
        }
        uint32_t bf[4][2];
#pragma unroll
        for (int nt = 0; nt < 4; nt++) {
            int col = wn + nt * 8 + tr;
            uint32_t b0 = Bs + ((k0 + tc) * LDB_S + col) * 4;
            bf[nt][0] = lds_u(b0);
            bf[nt][1] = lds_u(b0 + 4 * LDB_S * 4);
        }
#pragma unroll
        for (int mt = 0; mt < 4; mt++)
#pragma unroll
            for (int nt = 0; nt < 4; nt++)
                asm volatile(
                    "mma.sync.aligned.m16n8k8.row.col.f32.tf32.tf32.f32 "
                    "{%0,%1,%2,%3}, {%4,%5,%6,%7}, {%8,%9}, {%0,%1,%2,%3};"
                    : "+f"(acc[mt][nt][0]), "+f"(acc[mt][nt][1]),
                      "+f"(acc[mt][nt][2]), "+f"(acc[mt][nt][3])
                    : "r"(af[mt][0]), "r"(af[mt][1]), "r"(af[mt][2]), "r"(af[mt][3]),
                      "r"(bf[nt][0]), "r"(bf[nt][1]));
    }
}

__device__ __forceinline__ void mm_computeA(uint32_t Ab, uint32_t Bs, int kbase,
                                            int lane, int wm, int wn,
                                            float acc[4][4][4]) {
    int tr = lane >> 2, tc = lane & 3;
#pragma unroll
    for (int ks = 0; ks < 4; ks++) {
        int ka = kbase + ks * 8;
        int kb = ks * 8;
        uint32_t af[4][4];
#pragma unroll
        for (int mt = 0; mt < 4; mt++) {
            int row = wm + mt * 16 + tr;
            uint32_t b0 = Ab + (row * LDH + ka + tc) * 4;
            af[mt][0] = lds_u(b0);
            af[mt][1] = lds_u(b0 + 8 * LDH * 4);
            af[mt][2] = lds_u(b0 + 16);
            af[mt][3] = lds_u(b0 + 8 * LDH * 4 + 16);
        }
        uint32_t bf[4][2];
#pragma unroll
        for (int nt = 0; nt < 4; nt++) {
            int col = wn + nt * 8 + tr;
            uint32_t b0 = Bs + ((kb + tc) * LDB_S + col) * 4;
            bf[nt][0] = lds_u(b0);
            bf[nt][1] = lds_u(b0 + 4 * LDB_S * 4);
        }
#pragma unroll
        for (int mt = 0; mt < 4; mt++)
#pragma unroll
            for (int nt = 0; nt < 4; nt++)
                asm volatile(
                    "mma.sync.aligned.m16n8k8.row.col.f32.tf32.tf32.f32 "
                    "{%0,%1,%2,%3}, {%4,%5,%6,%7}, {%8,%9}, {%0,%1,%2,%3};"
                    : "+f"(acc[mt][nt][0]), "+f"(acc[mt][nt][1]),
                      "+f"(acc[mt][nt][2]), "+f"(acc[mt][nt][3])
                    : "r"(af[mt][0]), "r"(af[mt][1]), "r"(af[mt][2]), "r"(af[mt][3]),
                      "r"(bf[nt][0]), "r"(bf[nt][1]));
    }
}

#define ACC_INIT(acc) \
    _Pragma("unroll") for (int a_ = 0; a_ < 4; a_++) \
    _Pragma("unroll") for (int b_ = 0; b_ < 4; b_++) { \
        acc[a_][b_][0]=0.f; acc[a_][b_][1]=0.f; acc[a_][b_][2]=0.f; acc[a_][b_][3]=0.f; }

#define GEMM_MAINLOOP(Aptr, ldA, Bptr, ldB, bn0, NIT) do { \
    float4 vr[4]; \
    ldgA(Aptr, ldA, row0, 0, tid, vr); \
    cpB(aB[0], Bptr, ldB, bn0, 0, tid); \
    CP_COMMIT(); \
    stsA(aA[0], tid, vr); \
    CP_WAIT0(); \
    __syncthreads(); \
    int buf = 0; \
    for (int it = 0; it < (NIT); it++) { \
        bool pf = (it + 1 < (NIT)); \
        if (pf) { \
            ldgA(Aptr, ldA, row0, (it + 1) * 32, tid, vr); \
            cpB(aB[buf ^ 1], Bptr, ldB, bn0, (it + 1) * 32, tid); \
            CP_COMMIT(); \
        } \
        mm_compute(aA[buf], aB[buf], lane, wm, wn, acc); \
        if (pf) stsA(aA[buf ^ 1], tid, vr); \
        CP_WAIT0(); \
        __syncthreads(); \
        buf ^= 1; \
    } } while (0)

// ---------------------------------------------------------------------------
// GEMM1: h = LayerNorm(x @ W1 + b1)
// ---------------------------------------------------------------------------
__global__ __launch_bounds__(256) void k1_mma(
    const float* __restrict__ x, const float* __restrict__ b1,
    const float* __restrict__ ln_g, const float* __restrict__ ln_b)
{
    extern __shared__ char smraw[];
    SmemG* s = (SmemG*)smraw;
    int tid = threadIdx.x;
    int lane = tid & 31, wid = tid >> 5;
    int row0 = blockIdx.x * 128;
    int wm = (wid >> 2) * 64, wn = (wid & 3) * 32;

    if (tid < 128) {
        s->parb[tid]  = b1[tid];
        s->parg[tid]  = ln_g[tid];
        s->parbt[tid] = ln_b[tid];
    }
    uint32_t aA[2], aB[2];
    aA[0] = smem_u32(&s->u.mm.A[0][0]); aA[1] = smem_u32(&s->u.mm.A[1][0]);
    aB[0] = smem_u32(&s->u.mm.B[0][0]); aB[1] = smem_u32(&s->u.mm.B[1][0]);

    float acc[4][4][4];
    ACC_INIT(acc);
    GEMM_MAINLOOP(x, ND, g_W1r, NH, 0, ND / 32);

    int tr = lane >> 2, tc = lane & 3;
    float* epi = s->u.epi;
#pragma unroll
    for (int mt = 0; mt < 4; mt++) {
#pragma unroll
        for (int nt = 0; nt < 4; nt++) {
            int row = wm + mt * 16 + tr;
            int col = wn + nt * 8 + 2 * tc;
            float bb0 = s->parb[col], bb1 = s->parb[col + 1];
            epi[row * LDE_S + col]           = acc[mt][nt][0] + bb0;
            epi[row * LDE_S + col + 1]       = acc[mt][nt][1] + bb1;
            epi[(row + 8) * LDE_S + col]     = acc[mt][nt][2] + bb0;
            epi[(row + 8) * LDE_S + col + 1] = acc[mt][nt][3] + bb1;
        }
    }
    __syncthreads();

    for (int r = wid; r < 128; r += 8) {
        float x0 = epi[r * LDE_S + lane];
        float x1 = epi[r * LDE_S + lane + 32];
        float x2 = epi[r * LDE_S + lane + 64];
        float x3 = epi[r * LDE_S + lane + 96];
        float su = x0 + x1 + x2 + x3;
        float sq = x0 * x0 + x1 * x1 + x2 * x2 + x3 * x3;
#pragma unroll
        for (int o = 16; o; o >>= 1) {
            su += __shfl_xor_sync(0xffffffffu, su, o);
            sq += __shfl_xor_sync(0xffffffffu, sq, o);
        }
        float mean = su * (1.f / 128.f);
        float var  = sq * (1.f / 128.f) - mean * mean;
        if (lane == 0) {
            s->mean[r] = mean;
            s->rstd[r] = rsqrtf(fmaxf(var, 0.f) + 1e-5f);
        }
    }
    __syncthreads();

#pragma unroll
    for (int q = 0; q < 16; q++) {
        int idx = tid + 256 * q;
        int r = idx >> 5, c4 = idx & 31;
        int row = row0 + r;
        if (row < NM) {
            float4 v = *(float4*)&epi[r * LDE_S + 4 * c4];
            float mean = s->mean[r], rstd = s->rstd[r];
            float4 gv = *(float4*)&s->parg[4 * c4];
            float4 bv = *(float4*)&s->parbt[4 * c4];
            float4 o;
            o.x = (v.x - mean) * rstd * gv.x + bv.x;
            o.y = (v.y - mean) * rstd * gv.y + bv.y;
            o.z = (v.z - mean) * rstd * gv.z + bv.z;
            o.w = (v.w - mean) * rstd * gv.w + bv.w;
            *(float4*)(g_h + (size_t)row * NH + 4 * c4) = o;
        }
    }
}

// ---------------------------------------------------------------------------
// k_gateqkv: 4 batches per block; gate+LN in smem, qkv GEMM with resident A.
// ---------------------------------------------------------------------------
__global__ __launch_bounds__(256) void k_gateqkv(
    const float* __restrict__ T_W, const float* __restrict__ T_b,
    const float* __restrict__ n_g, const float* __restrict__ n_b)
{
    extern __shared__ char smraw[];
    SmemQ* s = (SmemQ*)smraw;
    int tid = threadIdx.x;
    int lane = tid & 31, wid = tid >> 5;
    int row0 = blockIdx.x * 4 * NT;   // 120 rows
    const float* hg = g_h + (size_t)row0 * NH;

    for (int i = tid; i < 384; i += 256) s->parb[i] = g_bqkv[i];

    for (int idx = tid; idx < 120 * 32; idx += 256) {
        int r = idx >> 5, c4 = idx & 31;
        float4 t = *(const float4*)(hg + (size_t)r * NH + 4 * c4);
        *(float4*)&s->hn[r * LDH + 4 * c4] = t;
    }
    for (int idx = tid; idx < 8 * 32; idx += 256) {
        int r = 120 + (idx >> 5), c4 = idx & 31;
        *(float4*)&s->hn[r * LDH + 4 * c4] = make_float4(0.f, 0.f, 0.f, 0.f);
    }
    __syncthreads();

    for (int r = wid; r < 120; r += 8) {
        float a = s->hn[r * LDH + lane] + s->hn[r * LDH + lane + 32]
                + s->hn[r * LDH + lane + 64] + s->hn[r * LDH + lane + 96];
#pragma unroll
        for (int o = 16; o; o >>= 1) a += __shfl_xor_sync(0xffffffffu, a, o);
        if (lane == 0) s->rowm[r] = a * (1.f / 128.f);
    }
    __syncthreads();

    if (wid < 4) {
        int bi = wid;
        float val = -1e30f;
        if (lane < NT) {
            float a = T_b[lane];
#pragma unroll
            for (int u = 0; u < NT; u++) a += s->rowm[bi * NT + u] * T_W[u * NT + lane];
            val = a;
        }
        float m = val;
#pragma unroll
        for (int o = 16; o; o >>= 1) m = fmaxf(m, __shfl_xor_sync(0xffffffffu, m, o));
        float e = (lane < NT) ? expf(val - m) : 0.f;
        float se = e;
#pragma unroll
        for (int o = 16; o; o >>= 1) se += __shfl_xor_sync(0xffffffffu, se, o);
        if (lane < NT) s->gate[bi * NT + lane] = e / se;
    }
    __syncthreads();

    float* hgo = g_hg + (size_t)row0 * NH;
    {
        float ng0 = n_g[lane], ng1 = n_g[lane + 32], ng2 = n_g[lane + 64], ng3 = n_g[lane + 96];
        float nb0 = n_b[lane], nb1 = n_b[lane + 32], nb2 = n_b[lane + 64], nb3 = n_b[lane + 96];
        for (int r = wid; r < 120; r += 8) {
            float gt = s->gate[r];
            float x0 = s->hn[r * LDH + lane]      * gt;
            float x1 = s->hn[r * LDH + lane + 32] * gt;
            float x2 = s->hn[r * LDH + lane + 64] * gt;
            float x3 = s->hn[r * LDH + lane + 96] * gt;
            hgo[r * NH + lane]      = x0;
            hgo[r * NH + lane + 32] = x1;
            hgo[r * NH + lane + 64] = x2;
            hgo[r * NH + lane + 96] = x3;
            float su = x0 + x1 + x2 + x3;
            float sq = x0 * x0 + x1 * x1 + x2 * x2 + x3 * x3;
#pragma unroll
            for (int o = 16; o; o >>= 1) {
                su += __shfl_xor_sync(0xffffffffu, su, o);
                sq += __shfl_xor_sync(0xffffffffu, sq, o);
            }
            float mean = su * (1.f / 128.f);
            float rstd = rsqrtf(sq * (1.f / 128.f) - mean * mean + 1e-5f);
            s->hn[r * LDH + lane]      = f2tf32f((x0 - mean) * rstd * ng0 + nb0);
            s->hn[r * LDH + lane + 32] = f2tf32f((x1 - mean) * rstd * ng1 + nb1);
            s->hn[r * LDH + lane + 64] = f2tf32f((x2 - mean) * rstd * ng2 + nb2);
            s->hn[r * LDH + lane + 96] = f2tf32f((x3 - mean) * rstd * ng3 + nb3);
        }
    }
    __syncthreads();

    int wm = (wid >> 2) * 64, wn = (wid & 3) * 32;
    int tr = lane >> 2, tc = lane & 3;
    uint32_t hnb = smem_u32(&s->hn[0]);
    uint32_t aB[2] = { smem_u32(&s->Bb[0][0]), smem_u32(&s->Bb[1][0]) };

    for (int ntile = 0; ntile < 3; ntile++) {
        int n0 = ntile * 128;
        float acc[4][4][4];
        ACC_INIT(acc);
        cpB(aB[0], g_Wqkvr, 384, n0, 0, tid); CP_COMMIT(); CP_WAIT0(); __syncthreads();
        int buf = 0;
        for (int it = 0; it < 4; it++) {
            if (it < 3) { cpB(aB[buf ^ 1], g_Wqkvr, 384, n0, (it + 1) * 32, tid); CP_COMMIT(); }
            mm_computeA(hnb, aB[buf], it * 32, lane, wm, wn, acc);
            CP_WAIT0(); __syncthreads();
            buf ^= 1;
        }
#pragma unroll
        for (int mt = 0; mt < 4; mt++) {
#pragma unroll
            for (int nt = 0; nt < 4; nt++) {
                int colL = wn + nt * 8 + 2 * tc;
                int col  = n0 + colL;
                float bb0 = s->parb[col], bb1 = s->parb[col + 1];
                int row = wm + mt * 16 + tr;
                if (row < 120)
                    *(float2*)(g_qkv + (size_t)(row0 + row) * 384 + col) =
                        make_float2(acc[mt][nt][0] + bb0, acc[mt][nt][1] + bb1);
                if (row + 8 < 120)
                    *(float2*)(g_qkv + (size_t)(row0 + row + 8) * 384 + col) =
                        make_float2(acc[mt][nt][2] + bb0, acc[mt][nt][3] + bb1);
            }
        }
    }
}

// ---------------------------------------------------------------------------
// k_att: per-batch scores + softmax + attn@v -> g_o (LDS-optimized)
// ---------------------------------------------------------------------------
struct SmemA {
    float q[NT][128];
    float kT[128][33];
    float v[NT][128];
    float sc[NT][32];
};
__global__ __launch_bounds__(256) void k_att()
{
    extern __shared__ char smraw[];
    SmemA* s = (SmemA*)smraw;
    int tid = threadIdx.x;
    int lane = tid & 31, wid = tid >> 5;
    int b = blockIdx.x;
    const float* qkv = g_qkv + (size_t)b * NT * 384;

    // load q/k/v; k transposed
    for (int idx = tid; idx < NT * 96; idx += 256) {
        int r = idx / 96, c4 = idx - (idx / 96) * 96;
        float4 t = *(const float4*)(qkv + (size_t)r * 384 + 4 * c4);
        if (c4 < 32) {
            *(float4*)&s->q[r][4 * c4] = t;
        } else if (c4 < 64) {
            int kc = 4 * (c4 - 32);
            s->kT[kc + 0][r] = t.x;
            s->kT[kc + 1][r] = t.y;
            s->kT[kc + 2][r] = t.z;
            s->kT[kc + 3][r] = t.w;
        } else {
            *(float4*)&s->v[r][4 * (c4 - 64)] = t;
        }
    }
    __syncthreads();

    const float SCALE = 0.08838834764831845f;  // sqrt(1/128)
    // scores: each warp computes 4 t-rows at once (t = wid + 8*i); one kT
    // load per j serves 4 rows -> LDS cut ~40%.
    {
        int t0 = wid, t1 = wid + 8, t2 = wid + 16, t3 = wid + 24;
        bool v3 = (t3 < NT);
        int t3c = v3 ? t3 : 0;
        float a0 = 0.f, a1 = 0.f, a2 = 0.f, a3 = 0.f;
#pragma unroll 16
        for (int j = 0; j < 128; j++) {
            float kv = s->kT[j][lane];
            a0 += s->q[t0][j] * kv;
            a1 += s->q[t1][j] * kv;
            a2 += s->q[t2][j] * kv;
            a3 += s->q[t3c][j] * kv;
        }
        // fused softmax per row
        float av[4] = {a0, a1, a2, a3};
        int   tv[4] = {t0, t1, t2, t3};
#pragma unroll
        for (int i = 0; i < 4; i++) {
            if (tv[i] >= NT) break;
            float val = (lane < NT) ? av[i] * SCALE : -1e30f;
            float m = val;
#pragma unroll
            for (int o = 16; o; o >>= 1) m = fmaxf(m, __shfl_xor_sync(0xffffffffu, m, o));
            float e = (lane < NT) ? expf(val - m) : 0.f;
            float se = e;
#pragma unroll
            for (int o = 16; o; o >>= 1) se += __shfl_xor_sync(0xffffffffu, se, o);
            s->sc[tv[i]][lane] = e / se;
        }
    }
    __syncthreads();

    // o = sc @ v : inverted loop, 15 accumulators, one v load per u.
    {
        int col = tid & 127, rp = tid >> 7;
        float accv[15];
#pragma unroll
        for (int j = 0; j < 15; j++) accv[j] = 0.f;
#pragma unroll
        for (int u = 0; u < NT; u++) {
            float vv = s->v[u][col];
#pragma unroll
            for (int j = 0; j < 15; j++)
                accv[j] += s->sc[rp + 2 * j][u] * vv;
        }
        float* ob = g_o + (size_t)b * NT * NH;
#pragma unroll
        for (int j = 0; j < 15; j++)
            ob[(rp + 2 * j) * NH + col] = accv[j];
    }
}

// ---------------------------------------------------------------------------
// k_oproj2: phase1 h = g_o @ Wo + bo + g_hg (smem, tf32-rounded);
//           phase2 out = h @ W2 + b2 over 8 N-tiles.
// ---------------------------------------------------------------------------
__global__ __launch_bounds__(256) void k_oproj2(
    const float* __restrict__ bo, const float* __restrict__ b2,
    float* __restrict__ out)
{
    extern __shared__ char smraw[];
    SmemO* s = (SmemO*)smraw;
    int tid = threadIdx.x;
    int lane = tid & 31, wid = tid >> 5;
    int row0 = blockIdx.x * 128;
    int wm = (wid >> 2) * 64, wn = (wid & 3) * 32;

    if (tid < 128) s->parb[tid] = bo[tid];
    uint32_t aA[2], aB[2];
    aA[0] = smem_u32(&s->a.Amm[0][0]); aA[1] = smem_u32(&s->a.Amm[1][0]);
    aB[0] = smem_u32(&s->Bb[0][0]);    aB[1] = smem_u32(&s->Bb[1][0]);

    float acc[4][4][4];
    ACC_INIT(acc);
    GEMM_MAINLOOP(g_o, NH, g_Wor, NH, 0, NH / 32);

    int tr = lane >> 2, tc = lane & 3;
#pragma unroll
    for (int mt = 0; mt < 4; mt++) {
#pragma unroll
        for (int nt = 0; nt < 4; nt++) {
            int colL = wn + nt * 8 + 2 * tc;
            float bb0 = s->parb[colL], bb1 = s->parb[colL + 1];
            int row = wm + mt * 16 + tr;
            {
                int grow = row0 + row;
                float v0 = 0.f, v1 = 0.f;
                if (grow < NM) {
                    float2 rres = *(const float2*)(g_hg + (size_t)grow * NH + colL);
                    v0 = acc[mt][nt][0] + bb0 + rres.x;
                    v1 = acc[mt][nt][1] + bb1 + rres.y;
                }
                s->a.hbuf[row * LDH + colL]     = f2tf32f(v0);
                s->a.hbuf[row * LDH + colL + 1] = f2tf32f(v1);
            }
            {
                int grow = row0 + row + 8;
                float v2 = 0.f, v3 = 0.f;
                if (grow < NM) {
                    float2 rres = *(const float2*)(g_hg + (size_t)grow * NH + colL);
                    v2 = acc[mt][nt][2] + bb0 + rres.x;
                    v3 = acc[mt][nt][3] + bb1 + rres.y;
                }
                s->a.hbuf[(row + 8) * LDH + colL]     = f2tf32f(v2);
                s->a.hbuf[(row + 8) * LDH + colL + 1] = f2tf32f(v3);
            }
        }
    }
    __syncthreads();

    uint32_t hb = smem_u32(&s->a.hbuf[0]);
    for (int ntile = 0; ntile < 8; ntile++) {
        int n0 = ntile * 128;
        ACC_INIT(acc);
        cpB(aB[0], g_W2r, ND, n0, 0, tid); CP_COMMIT(); CP_WAIT0(); __syncthreads();
        int buf = 0;
        for (int it = 0; it < 4; it++) {
            if (it < 3) { cpB(aB[buf ^ 1], g_W2r, ND, n0, (it + 1) * 32, tid); CP_COMMIT(); }
            mm_computeA(hb, aB[buf], it * 32, lane, wm, wn, acc);
            CP_WAIT0(); __syncthreads();
            buf ^= 1;
        }
#pragma unroll
        for (int mt = 0; mt < 4; mt++) {
#pragma unroll
            for (int nt = 0; nt < 4; nt++) {
                int colL = wn + nt * 8 + 2 * tc;
                int col  = n0 + colL;
                float bb0 = __ldg(b2 + col), bb1 = __ldg(b2 + col + 1);
                int row = row0 + wm + mt * 16 + tr;
                if (row < NM)
                    *(float2*)(out + (size_t)row * ND + col) =
                        make_float2(acc[mt][nt][0] + bb0, acc[mt][nt][1] + bb1);
                if (row + 8 < NM)
                    *(float2*)(out + (size_t)(row + 8) * ND + col) =
                        make_float2(acc[mt][nt][2] + bb0, acc[mt][nt][3] + bb1);
            }
        }
    }
}

// ---------------------------------------------------------------------------
extern "C" void kernel_launch(void* const* d_in, const int* in_sizes, int n_in,
                              void* d_out, int out_size)
{
    const float* x    = (const float*)d_in[0];
    const float* W1   = (const float*)d_in[1];
    const float* b1   = (const float*)d_in[2];
    const float* ln_g = (const float*)d_in[3];
    const float* ln_b = (const float*)d_in[4];
    const float* T_W  = (const float*)d_in[5];
    const float* T_b  = (const float*)d_in[6];
    const float* Wq   = (const float*)d_in[7];
    const float* bq   = (const float*)d_in[8];
    const float* Wk   = (const float*)d_in[9];
    const float* bk   = (const float*)d_in[10];
    const float* Wv   = (const float*)d_in[11];
    const float* bv   = (const float*)d_in[12];
    const float* Wo   = (const float*)d_in[13];
    const float* bo   = (const float*)d_in[14];
    const float* n_g  = (const float*)d_in[15];
    const float* n_b  = (const float*)d_in[16];
    const float* W2   = (const float*)d_in[17];
    const float* b2   = (const float*)d_in[18];
    float* out = (float*)d_out;

    int dynG = (int)sizeof(SmemG);
    int dynQ = (int)sizeof(SmemQ);
    int dynA = (int)sizeof(SmemA);
    int dynO = (int)sizeof(SmemO);
    cudaFuncSetAttribute(k1_mma,    cudaFuncAttributeMaxDynamicSharedMemorySize, dynG);
    cudaFuncSetAttribute(k_gateqkv, cudaFuncAttributeMaxDynamicSharedMemorySize, dynQ);
    cudaFuncSetAttribute(k_att,     cudaFuncAttributeMaxDynamicSharedMemorySize, dynA);
    cudaFuncSetAttribute(k_oproj2,  cudaFuncAttributeMaxDynamicSharedMemorySize, dynO);

    const int PREP_N = ND * NH + NH * ND + NH * NH + 3 * NH * NH + 384;
    k_prep<<<(PREP_N + 255) / 256, 256>>>(W1, W2, Wo, Wq, Wk, Wv, bq, bk, bv);

    int gm = (NM + 127) / 128;  // 370
    k1_mma<<<gm, 256, dynG>>>(x, b1, ln_g, ln_b);
    k_gateqkv<<<NB / 4, 256, dynQ>>>(T_W, T_b, n_g, n_b);
    k_att<<<NB, 256, dynA>>>();
    k_oproj2<<<gm, 256, dynO>>>(bo, b2, out);
}

// round 15
// speedup vs baseline: 3.7872x; 1.2805x over previous
#include <cuda_runtime.h>
#include <math.h>
#include <stdint.h>

#define NB 1576
#define NT 30
#define ND 1024
#define NH 128
#define NM (NB*NT)   // 47280

// scratch
__device__ float g_h  [(size_t)NM * NH];
__device__ float g_hg [(size_t)NM * NH];
__device__ float g_o  [(size_t)NM * NH];
__device__ float g_qkv[(size_t)NM * 384];
__device__ float g_W1r[(size_t)ND * NH];
__device__ float g_W2r[(size_t)NH * ND];
__device__ float g_Wor[(size_t)NH * NH];
__device__ float g_Wqkvr[(size_t)NH * 384];
__device__ float g_bqkv[384];

__device__ __forceinline__ uint32_t smem_u32(const void* p) {
    uint32_t a;
    asm("{ .reg .u64 t; cvta.to.shared.u64 t, %1; cvt.u32.u64 %0, t; }" : "=r"(a) : "l"(p));
    return a;
}
__device__ __forceinline__ uint32_t f2tf32(float f) {
    uint32_t r; asm("cvt.rna.tf32.f32 %0, %1;" : "=r"(r) : "f"(f)); return r;
}
__device__ __forceinline__ float f2tf32f(float f) { return __uint_as_float(f2tf32(f)); }
__device__ __forceinline__ uint32_t cvt_raw_tf32(uint32_t raw) {
    uint32_t r; asm("cvt.rna.tf32.f32 %0, %1;" : "=r"(r) : "f"(__uint_as_float(raw)));
    return r;
}
__device__ __forceinline__ void sts128(uint32_t a, uint32_t x, uint32_t y, uint32_t z, uint32_t w) {
    asm volatile("st.shared.v4.b32 [%0], {%1,%2,%3,%4};" :: "r"(a), "r"(x), "r"(y), "r"(z), "r"(w));
}
__device__ __forceinline__ uint32_t lds_u(uint32_t a) {
    uint32_t v; asm volatile("ld.shared.b32 %0, [%1];" : "=r"(v) : "r"(a)); return v;
}
__device__ __forceinline__ void cp16(uint32_t dst, const void* src) {
    asm volatile("cp.async.cg.shared.global [%0], [%1], 16;" :: "r"(dst), "l"(src));
}
__device__ __forceinline__ void cp16z(uint32_t dst, const void* src, uint32_t sz) {
    asm volatile("cp.async.cg.shared.global [%0], [%1], 16, %2;"
                 :: "r"(dst), "l"(src), "r"(sz));
}
#define CP_COMMIT() asm volatile("cp.async.commit_group;" ::: "memory")
#define CP_WAIT0()  asm volatile("cp.async.wait_group 0;" ::: "memory")

#define LDA_S 36
#define LDB_S 136
#define LDE_S 132
#define LDH   132
#define M1    160
#define GM1   296

#define K1_A0   0
#define K1_A1   (M1*LDA_S)
#define K1_B0   (2*M1*LDA_S)
#define K1_B1   (2*M1*LDA_S + 32*LDB_S)
#define K1_UNION 21120
struct SmemG1 {
    float u[K1_UNION];
    float parb[128];
    float parg[128];
    float parbt[128];
    float mean[M1];
    float rstd[M1];
};
struct SmemO2 {
    float u[K1_UNION];
    float Bb[32 * LDB_S];
    float parb[128];
};
struct SmemQ {
    float hn[128 * LDH];
    float Bb[2][32 * LDB_S];
    float rowm[120];
    float gate[120];
    float parb[384];
};

__global__ void k_prep(const float* __restrict__ W1, const float* __restrict__ W2,
                       const float* __restrict__ Wo,
                       const float* __restrict__ Wq, const float* __restrict__ Wk,
                       const float* __restrict__ Wv,
                       const float* __restrict__ bq, const float* __restrict__ bk,
                       const float* __restrict__ bv) {
    int i = blockIdx.x * 256 + threadIdx.x;
    const int N1 = ND * NH, N2 = NH * ND, N3 = NH * NH, N4 = 3 * NH * NH;
    if (i < N1) {
        g_W1r[i] = f2tf32f(W1[i]);
    } else if (i < N1 + N2) {
        int j = i - N1;
        g_W2r[j] = f2tf32f(W2[j]);
    } else if (i < N1 + N2 + N3) {
        int j = i - N1 - N2;
        g_Wor[j] = f2tf32f(Wo[j]);
    } else if (i < N1 + N2 + N3 + N4) {
        int j = i - N1 - N2 - N3;
        int m = j / (NH * NH);
        int r = (j / NH) % NH;
        int n = j % NH;
        const float* W = (m == 0) ? Wq : (m == 1) ? Wk : Wv;
        g_Wqkvr[(size_t)r * 384 + m * NH + n] = f2tf32f(W[(size_t)r * NH + n]);
    } else if (i < N1 + N2 + N3 + N4 + 384) {
        int j = i - N1 - N2 - N3 - N4;
        int m = j / NH, n = j % NH;
        const float* bb = (m == 0) ? bq : (m == 1) ? bk : bv;
        g_bqkv[j] = bb[n];
    }
}

__device__ __forceinline__ void cpA(uint32_t As, const float* __restrict__ Ag,
                                    int ldA, int row0, int k0, int tid) {
#pragma unroll
    for (int q = 0; q < 5; q++) {
        int idx = tid + 256 * q;
        int r = idx >> 3, j = idx & 7;
        int row = row0 + r;
        uint32_t sz = (row < NM) ? 16u : 0u;
        const float* src = Ag + (size_t)(row < NM ? row : 0) * ldA + k0 + j * 4;
        cp16z(As + (r * LDA_S + j * 4) * 4, src, sz);
    }
}
__device__ __forceinline__ void cpB(uint32_t Bs, const float* __restrict__ Bg,
                                    int ldB, int bn0, int k0, int tid) {
#pragma unroll
    for (int q = 0; q < 4; q++) {
        int idx = tid + 256 * q;
        int kk = idx >> 5, jc = idx & 31;
        cp16(Bs + (kk * LDB_S + jc * 4) * 4,
             Bg + (size_t)(k0 + kk) * ldB + bn0 + jc * 4);
    }
}

template<int MT, int LD, bool CVT>
__device__ __forceinline__ void mm_frag(uint32_t Ab, uint32_t Bs, int kbase,
                                        int lane, int wm, int wn,
                                        float acc[MT][4][4]) {
    int tr = lane >> 2, tc = lane & 3;
#pragma unroll
    for (int ks = 0; ks < 4; ks++) {
        int ka = kbase + ks * 8;
        int kb = ks * 8;
        uint32_t af[MT][4];
#pragma unroll
        for (int mt = 0; mt < MT; mt++) {
            int row = wm + mt * 16 + tr;
            uint32_t b0 = Ab + (row * LD + ka + tc) * 4;
            af[mt][0] = lds_u(b0);
            af[mt][1] = lds_u(b0 + 8 * LD * 4);
            af[mt][2] = lds_u(b0 + 16);
            af[mt][3] = lds_u(b0 + 8 * LD * 4 + 16);
            if (CVT) {
                af[mt][0] = cvt_raw_tf32(af[mt][0]);
                af[mt][1] = cvt_raw_tf32(af[mt][1]);
                af[mt][2] = cvt_raw_tf32(af[mt][2]);
                af[mt][3] = cvt_raw_tf32(af[mt][3]);
            }
        }
        uint32_t bf[4][2];
#pragma unroll
        for (int nt = 0; nt < 4; nt++) {
            int col = wn + nt * 8 + tr;
            uint32_t b0 = Bs + ((kb + tc) * LDB_S + col) * 4;
            bf[nt][0] = lds_u(b0);
            bf[nt][1] = lds_u(b0 + 4 * LDB_S * 4);
        }
#pragma unroll
        for (int mt = 0; mt < MT; mt++)
#pragma unroll
            for (int nt = 0; nt < 4; nt++)
                asm volatile(
                    "mma.sync.aligned.m16n8k8.row.col.f32.tf32.tf32.f32 "
                    "{%0,%1,%2,%3}, {%4,%5,%6,%7}, {%8,%9}, {%0,%1,%2,%3};"
                    : "+f"(acc[mt][nt][0]), "+f"(acc[mt][nt][1]),
                      "+f"(acc[mt][nt][2]), "+f"(acc[mt][nt][3])
                    : "r"(af[mt][0]), "r"(af[mt][1]), "r"(af[mt][2]), "r"(af[mt][3]),
                      "r"(bf[nt][0]), "r"(bf[nt][1]));
    }
}

#define ACC_INIT5(acc) \
    _Pragma("unroll") for (int a_ = 0; a_ < 5; a_++) \
    _Pragma("unroll") for (int b_ = 0; b_ < 4; b_++) { \
        acc[a_][b_][0]=0.f; acc[a_][b_][1]=0.f; acc[a_][b_][2]=0.f; acc[a_][b_][3]=0.f; }
#define ACC_INIT4(acc) \
    _Pragma("unroll") for (int a_ = 0; a_ < 4; a_++) \
    _Pragma("unroll") for (int b_ = 0; b_ < 4; b_++) { \
        acc[a_][b_][0]=0.f; acc[a_][b_][1]=0.f; acc[a_][b_][2]=0.f; acc[a_][b_][3]=0.f; }

__global__ __launch_bounds__(256, 2) void k1_mma(
    const float* __restrict__ x, const float* __restrict__ b1,
    const float* __restrict__ ln_g, const float* __restrict__ ln_b)
{
    extern __shared__ char smraw[];
    SmemG1* s = (SmemG1*)smraw;
    int tid = threadIdx.x;
    int lane = tid & 31, wid = tid >> 5;
    int row0 = blockIdx.x * M1;
    int wm = (wid >> 2) * 80, wn = (wid & 3) * 32;

    if (tid < 128) {
        s->parb[tid]  = b1[tid];
        s->parg[tid]  = ln_g[tid];
        s->parbt[tid] = ln_b[tid];
    }
    uint32_t ub = smem_u32(&s->u[0]);
    uint32_t aA[2] = { ub + K1_A0 * 4, ub + K1_A1 * 4 };
    uint32_t aB[2] = { ub + K1_B0 * 4, ub + K1_B1 * 4 };

    float acc[5][4][4];
    ACC_INIT5(acc);

    cpA(aA[0], x, ND, row0, 0, tid);
    cpB(aB[0], g_W1r, NH, 0, 0, tid);
    CP_COMMIT(); CP_WAIT0();
    __syncthreads();

    int buf = 0;
    for (int it = 0; it < ND / 32; it++) {
        bool pf = (it + 1 < ND / 32);
        if (pf) {
            cpA(aA[buf ^ 1], x, ND, row0, (it + 1) * 32, tid);
            cpB(aB[buf ^ 1], g_W1r, NH, 0, (it + 1) * 32, tid);
            CP_COMMIT();
        }
        mm_frag<5, LDA_S, true>(aA[buf], aB[buf], 0, lane, wm, wn, acc);
        CP_WAIT0();
        __syncthreads();
        buf ^= 1;
    }

    int tr = lane >> 2, tc = lane & 3;
    float* epi = s->u;
#pragma unroll
    for (int mt = 0; mt < 5; mt++) {
#pragma unroll
        for (int nt = 0; nt < 4; nt++) {
            int row = wm + mt * 16 + tr;
            int col = wn + nt * 8 + 2 * tc;
            float bb0 = s->parb[col], bb1 = s->parb[col + 1];
            epi[row * LDE_S + col]           = acc[mt][nt][0] + bb0;
            epi[row * LDE_S + col + 1]       = acc[mt][nt][1] + bb1;
            epi[(row + 8) * LDE_S + col]     = acc[mt][nt][2] + bb0;
            epi[(row + 8) * LDE_S + col + 1] = acc[mt][nt][3] + bb1;
        }
    }
    __syncthreads();

    for (int r = wid; r < M1; r += 8) {
        float x0 = epi[r * LDE_S + lane];
        float x1 = epi[r * LDE_S + lane + 32];
        float x2 = epi[r * LDE_S + lane + 64];
        float x3 = epi[r * LDE_S + lane + 96];
        float su = x0 + x1 + x2 + x3;
        float sq = x0 * x0 + x1 * x1 + x2 * x2 + x3 * x3;
#pragma unroll
        for (int o = 16; o; o >>= 1) {
            su += __shfl_xor_sync(0xffffffffu, su, o);
            sq += __shfl_xor_sync(0xffffffffu, sq, o);
        }
        float mean = su * (1.f / 128.f);
        float var  = sq * (1.f / 128.f) - mean * mean;
        if (lane == 0) {
            s->mean[r] = mean;
            s->rstd[r] = rsqrtf(fmaxf(var, 0.f) + 1e-5f);
        }
    }
    __syncthreads();

#pragma unroll
    for (int q = 0; q < 20; q++) {
        int idx = tid + 256 * q;
        int r = idx >> 5, c4 = idx & 31;
        int row = row0 + r;
        if (row < NM) {
            float4 v = *(float4*)&epi[r * LDE_S + 4 * c4];
            float mean = s->mean[r], rstd = s->rstd[r];
            float4 gv = *(float4*)&s->parg[4 * c4];
            float4 bv = *(float4*)&s->parbt[4 * c4];
            float4 o;
            o.x = (v.x - mean) * rstd * gv.x + bv.x;
            o.y = (v.y - mean) * rstd * gv.y + bv.y;
            o.z = (v.z - mean) * rstd * gv.z + bv.z;
            o.w = (v.w - mean) * rstd * gv.w + bv.w;
            *(float4*)(g_h + (size_t)row * NH + 4 * c4) = o;
        }
    }
}

__global__ __launch_bounds__(256) void k_gateqkv(
    const float* __restrict__ T_W, const float* __restrict__ T_b,
    const float* __restrict__ n_g, const float* __restrict__ n_b)
{
    extern __shared__ char smraw[];
    SmemQ* s = (SmemQ*)smraw;
    int tid = threadIdx.x;
    int lane = tid & 31, wid = tid >> 5;
    int row0 = blockIdx.x * 4 * NT;
    const float* hg = g_h + (size_t)row0 * NH;

    for (int i = tid; i < 384; i += 256) s->parb[i] = g_bqkv[i];

    for (int idx = tid; idx < 120 * 32; idx += 256) {
        int r = idx >> 5, c4 = idx & 31;
        float4 t = *(const float4*)(hg + (size_t)r * NH + 4 * c4);
        *(float4*)&s->hn[r * LDH + 4 * c4] = t;
    }
    for (int idx = tid; idx < 8 * 32; idx += 256) {
        int r = 120 + (idx >> 5), c4 = idx & 31;
        *(float4*)&s->hn[r * LDH + 4 * c4] = make_float4(0.f, 0.f, 0.f, 0.f);
    }
    __syncthreads();

    for (int r = wid; r < 120; r += 8) {
        float a = s->hn[r * LDH + lane] + s->hn[r * LDH + lane + 32]
                + s->hn[r * LDH + lane + 64] + s->hn[r * LDH + lane + 96];
#pragma unroll
        for (int o = 16; o; o >>= 1) a += __shfl_xor_sync(0xffffffffu, a, o);
        if (lane == 0) s->rowm[r] = a * (1.f / 128.f);
    }
    __syncthreads();

    if (wid < 4) {
        int bi = wid;
        float val = -1e30f;
        if (lane < NT) {
            float a = T_b[lane];
#pragma unroll
            for (int u = 0; u < NT; u++) a += s->rowm[bi * NT + u] * T_W[u * NT + lane];
            val = a;
        }
        float m = val;
#pragma unroll
        for (int o = 16; o; o >>= 1) m = fmaxf(m, __shfl_xor_sync(0xffffffffu, m, o));
        float e = (lane < NT) ? expf(val - m) : 0.f;
        float se = e;
#pragma unroll
        for (int o = 16; o; o >>= 1) se += __shfl_xor_sync(0xffffffffu, se, o);
        if (lane < NT) s->gate[bi * NT + lane] = e / se;
    }
    __syncthreads();

    float* hgo = g_hg + (size_t)row0 * NH;
    {
        float ng0 = n_g[lane], ng1 = n_g[lane + 32], ng2 = n_g[lane + 64], ng3 = n_g[lane + 96];
        float nb0 = n_b[lane], nb1 = n_b[lane + 32], nb2 = n_b[lane + 64], nb3 = n_b[lane + 96];
        for (int r = wid; r < 120; r += 8) {
            float gt = s->gate[r];
            float x0 = s->hn[r * LDH + lane]      * gt;
            float x1 = s->hn[r * LDH + lane + 32] * gt;
            float x2 = s->hn[r * LDH + lane + 64] * gt;
            float x3 = s->hn[r * LDH + lane + 96] * gt;
            hgo[r * NH + lane]      = x0;
            hgo[r * NH + lane + 32] = x1;
            hgo[r * NH + lane + 64] = x2;
            hgo[r * NH + lane + 96] = x3;
            float su = x0 + x1 + x2 + x3;
            float sq = x0 * x0 + x1 * x1 + x2 * x2 + x3 * x3;
#pragma unroll
            for (int o = 16; o; o >>= 1) {
                su += __shfl_xor_sync(0xffffffffu, su, o);
                sq += __shfl_xor_sync(0xffffffffu, sq, o);
            }
            float mean = su * (1.f / 128.f);
            float rstd = rsqrtf(sq * (1.f / 128.f) - mean * mean + 1e-5f);
            s->hn[r * LDH + lane]      = f2tf32f((x0 - mean) * rstd * ng0 + nb0);
            s->hn[r * LDH + lane + 32] = f2tf32f((x1 - mean) * rstd * ng1 + nb1);
            s->hn[r * LDH + lane + 64] = f2tf32f((x2 - mean) * rstd * ng2 + nb2);
            s->hn[r * LDH + lane + 96] = f2tf32f((x3 - mean) * rstd * ng3 + nb3);
        }
    }
    __syncthreads();

    int wm = (wid >> 2) * 64, wn = (wid & 3) * 32;
    int tr = lane >> 2, tc = lane & 3;
    uint32_t hnb = smem_u32(&s->hn[0]);
    uint32_t aB[2] = { smem_u32(&s->Bb[0][0]), smem_u32(&s->Bb[1][0]) };

    for (int ntile = 0; ntile < 3; ntile++) {
        int n0 = ntile * 128;
        float acc[4][4][4];
        ACC_INIT4(acc);
        cpB(aB[0], g_Wqkvr, 384, n0, 0, tid); CP_COMMIT(); CP_WAIT0(); __syncthreads();
        int buf = 0;
        for (int it = 0; it < 4; it++) {
            if (it < 3) { cpB(aB[buf ^ 1], g_Wqkvr, 384, n0, (it + 1) * 32, tid); CP_COMMIT(); }
            mm_frag<4, LDH, false>(hnb, aB[buf], it * 32, lane, wm, wn, acc);
            CP_WAIT0(); __syncthreads();
            buf ^= 1;
        }
#pragma unroll
        for (int mt = 0; mt < 4; mt++) {
#pragma unroll
            for (int nt = 0; nt < 4; nt++) {
                int colL = wn + nt * 8 + 2 * tc;
                int col  = n0 + colL;
                float bb0 = s->parb[col], bb1 = s->parb[col + 1];
                int row = wm + mt * 16 + tr;
                if (row < 120)
                    *(float2*)(g_qkv + (size_t)(row0 + row) * 384 + col) =
                        make_float2(acc[mt][nt][0] + bb0, acc[mt][nt][1] + bb1);
                if (row + 8 < 120)
                    *(float2*)(g_qkv + (size_t)(row0 + row + 8) * 384 + col) =
                        make_float2(acc[mt][nt][2] + bb0, acc[mt][nt][3] + bb1);
            }
        }
    }
}

struct SmemA {
    float q[NT][128];
    float kT[128][33];
    float v[NT][128];
    float sc[NT][32];
};
__global__ __launch_bounds__(256) void k_att()
{
    extern __shared__ char smraw[];
    SmemA* s = (SmemA*)smraw;
    int tid = threadIdx.x;
    int lane = tid & 31, wid = tid >> 5;
    int b = blockIdx.x;
    const float* qkv = g_qkv + (size_t)b * NT * 384;

    for (int idx = tid; idx < NT * 96; idx += 256) {
        int r = idx / 96, c4 = idx - (idx / 96) * 96;
        float4 t = *(const float4*)(qkv + (size_t)r * 384 + 4 * c4);
        if (c4 < 32) {
            *(float4*)&s->q[r][4 * c4] = t;
        } else if (c4 < 64) {
            int kc = 4 * (c4 - 32);
            s->kT[kc + 0][r] = t.x;
            s->kT[kc + 1][r] = t.y;
            s->kT[kc + 2][r] = t.z;
            s->kT[kc + 3][r] = t.w;
        } else {
            *(float4*)&s->v[r][4 * (c4 - 64)] = t;
        }
    }
    __syncthreads();

    const float SCALE = 0.08838834764831845f;
    {
        int t0 = wid, t1 = wid + 8, t2 = wid + 16, t3 = wid + 24;
        bool v3 = (t3 < NT);
        int t3c = v3 ? t3 : 0;
        float a0 = 0.f, a1 = 0.f, a2 = 0.f, a3 = 0.f;
#pragma unroll 16
        for (int j = 0; j < 128; j++) {
            float kv = s->kT[j][lane];
            a0 += s->q[t0][j] * kv;
            a1 += s->q[t1][j] * kv;
            a2 += s->q[t2][j] * kv;
            a3 += s->q[t3c][j] * kv;
        }
        float av[4] = {a0, a1, a2, a3};
        int   tv[4] = {t0, t1, t2, t3};
#pragma unroll
        for (int i = 0; i < 4; i++) {
            if (tv[i] >= NT) break;
            float val = (lane < NT) ? av[i] * SCALE : -1e30f;
            float m = val;
#pragma unroll
            for (int o = 16; o; o >>= 1) m = fmaxf(m, __shfl_xor_sync(0xffffffffu, m, o));
            float e = (lane < NT) ? expf(val - m) : 0.f;
            float se = e;
#pragma unroll
            for (int o = 16; o; o >>= 1) se += __shfl_xor_sync(0xffffffffu, se, o);
            s->sc[tv[i]][lane] = e / se;
        }
    }
    __syncthreads();

    {
        int col = tid & 127, rp = tid >> 7;
        float accv[15];
#pragma unroll
        for (int j = 0; j < 15; j++) accv[j] = 0.f;
#pragma unroll
        for (int u = 0; u < NT; u++) {
            float vv = s->v[u][col];
#pragma unroll
            for (int j = 0; j < 15; j++)
                accv[j] += s->sc[rp + 2 * j][u] * vv;
        }
        float* ob = g_o + (size_t)b * NT * NH;
#pragma unroll
        for (int j = 0; j < 15; j++)
            ob[(rp + 2 * j) * NH + col] = accv[j];
    }
}

__global__ __launch_bounds__(256, 2) void k_oproj2(
    const float* __restrict__ bo, const float* __restrict__ b2,
    float* __restrict__ out)
{
    extern __shared__ char smraw[];
    SmemO2* s = (SmemO2*)smraw;
    int tid = threadIdx.x;
    int lane = tid & 31, wid = tid >> 5;
    int row0 = blockIdx.x * M1;
    int wm = (wid >> 2) * 80, wn = (wid & 3) * 32;

    if (tid < 128) s->parb[tid] = bo[tid];
    uint32_t ub = smem_u32(&s->u[0]);
    uint32_t aA[2] = { ub + K1_A0 * 4, ub + K1_A1 * 4 };
    uint32_t aB[2] = { ub + K1_B0 * 4, ub + K1_B1 * 4 };

    float acc[5][4][4];
    ACC_INIT5(acc);

    cpA(aA[0], g_o, NH, row0, 0, tid);
    cpB(aB[0], g_Wor, NH, 0, 0, tid);
    CP_COMMIT(); CP_WAIT0();
    __syncthreads();

    int buf = 0;
    for (int it = 0; it < 4; it++) {
        bool pf = (it + 1 < 4);
        if (pf) {
            cpA(aA[buf ^ 1], g_o, NH, row0, (it + 1) * 32, tid);
            cpB(aB[buf ^ 1], g_Wor, NH, 0, (it + 1) * 32, tid);
            CP_COMMIT();
        }
        mm_frag<5, LDA_S, true>(aA[buf], aB[buf], 0, lane, wm, wn, acc);
        CP_WAIT0();
        __syncthreads();
        buf ^= 1;
    }

    int tr = lane >> 2, tc = lane & 3;
    float* hbuf = s->u;
#pragma unroll
    for (int mt = 0; mt < 5; mt++) {
#pragma unroll
        for (int nt = 0; nt < 4; nt++) {
            int colL = wn + nt * 8 + 2 * tc;
            float bb0 = s->parb[colL], bb1 = s->parb[colL + 1];
            int row = wm + mt * 16 + tr;
            {
                int grow = row0 + row;
                float v0 = 0.f, v1 = 0.f;
                if (grow < NM) {
                    float2 rres = *(const float2*)(g_hg + (size_t)grow * NH + colL);
                    v0 = acc[mt][nt][0] + bb0 + rres.x;
                    v1 = acc[mt][nt][1] + bb1 + rres.y;
                }
                hbuf[row * LDE_S + colL]     = f2tf32f(v0);
                hbuf[row * LDE_S + colL + 1] = f2tf32f(v1);
            }
            {
                int grow = row0 + row + 8;
                float v2 = 0.f, v3 = 0.f;
                if (grow < NM) {
                    float2 rres = *(const float2*)(g_hg + (size_t)grow * NH + colL);
                    v2 = acc[mt][nt][2] + bb0 + rres.x;
                    v3 = acc[mt][nt][3] + bb1 + rres.y;
                }
                hbuf[(row + 8) * LDE_S + colL]     = f2tf32f(v2);
                hbuf[(row + 8) * LDE_S + colL + 1] = f2tf32f(v3);
            }
        }
    }
    __syncthreads();

    uint32_t hb = ub;
    uint32_t Bb = smem_u32(&s->Bb[0]);

    float4 vrB[4];
#pragma unroll
    for (int q = 0; q < 4; q++) {
        int idx = tid + 256 * q;
        int kk = idx >> 5, jc = idx & 31;
        vrB[q] = *(const float4*)(g_W2r + (size_t)kk * ND + jc * 4);
    }
#pragma unroll
    for (int q = 0; q < 4; q++) {
        int idx = tid + 256 * q;
        int kk = idx >> 5, jc = idx & 31;
        sts128(Bb + (kk * LDB_S + jc * 4) * 4,
               __float_as_uint(vrB[q].x), __float_as_uint(vrB[q].y),
               __float_as_uint(vrB[q].z), __float_as_uint(vrB[q].w));
    }
    __syncthreads();

    ACC_INIT5(acc);
    for (int c = 0; c < 32; c++) {
        int nt = c >> 2, it = c & 3;
        if (c + 1 < 32) {
            int nt2 = (c + 1) >> 2, it2 = (c + 1) & 3;
            int n0 = nt2 * 128, k0 = it2 * 32;
#pragma unroll
            for (int q = 0; q < 4; q++) {
                int idx = tid + 256 * q;
                int kk = idx >> 5, jc = idx & 31;
                vrB[q] = *(const float4*)(g_W2r + (size_t)(k0 + kk) * ND + n0 + jc * 4);
            }
        }
        mm_frag<5, LDE_S, false>(hb, Bb, it * 32, lane, wm, wn, acc);

        if (it == 3) {
            int n0 = nt * 128;
#pragma unroll
            for (int mt = 0; mt < 5; mt++) {
#pragma unroll
                for (int nt2 = 0; nt2 < 4; nt2++) {
                    int colL = wn + nt2 * 8 + 2 * tc;
                    int col  = n0 + colL;
                    float bb0 = __ldg(b2 + col), bb1 = __ldg(b2 + col + 1);
                    int row = row0 + wm + mt * 16 + tr;
                    if (row < NM)
                        *(float2*)(out + (size_t)row * ND + col) =
                            make_float2(acc[mt][nt2][0] + bb0, acc[mt][nt2][1] + bb1);
                    if (row + 8 < NM)
                        *(float2*)(out + (size_t)(row + 8) * ND + col) =
                            make_float2(acc[mt][nt2][2] + bb0, acc[mt][nt2][3] + bb1);
                }
            }
            ACC_INIT5(acc);
        }
        __syncthreads();
        if (c + 1 < 32) {
#pragma unroll
            for (int q = 0; q < 4; q++) {
                int idx = tid + 256 * q;
                int kk = idx >> 5, jc = idx & 31;
                sts128(Bb + (kk * LDB_S + jc * 4) * 4,
                       __float_as_uint(vrB[q].x), __float_as_uint(vrB[q].y),
                       __float_as_uint(vrB[q].z), __float_as_uint(vrB[q].w));
            }
            __syncthreads();
        }
    }
}

extern "C" void kernel_launch(void* const* d_in, const int* in_sizes, int n_in,
                              void* d_out, int out_size)
{
    const float* x    = (const float*)d_in[0];
    const float* W1   = (const float*)d_in[1];
    const float* b1   = (const float*)d_in[2];
    const float* ln_g = (const float*)d_in[3];
    const float* ln_b = (const float*)d_in[4];
    const float* T_W  = (const float*)d_in[5];
    const float* T_b  = (const float*)d_in[6];
    const float* Wq   = (const float*)d_in[7];
    const float* bq   = (const float*)d_in[8];
    const float* Wk   = (const float*)d_in[9];
    const float* bk   = (const float*)d_in[10];
    const float* Wv   = (const float*)d_in[11];
    const float* bv   = (const float*)d_in[12];
    const float* Wo   = (const float*)d_in[13];
    const float* bo   = (const float*)d_in[14];
    const float* n_g  = (const float*)d_in[15];
    const float* n_b  = (const float*)d_in[16];
    const float* W2   = (const float*)d_in[17];
    const float* b2   = (const float*)d_in[18];
    float* out = (float*)d_out;

    int dynG1 = (int)sizeof(SmemG1);
    int dynQ  = (int)sizeof(SmemQ);
    int dynA  = (int)sizeof(SmemA);
    int dynO2 = (int)sizeof(SmemO2);
    cudaFuncSetAttribute(k1_mma,    cudaFuncAttributeMaxDynamicSharedMemorySize, dynG1);
    cudaFuncSetAttribute(k_gateqkv, cudaFuncAttributeMaxDynamicSharedMemorySize, dynQ);
    cudaFuncSetAttribute(k_att,     cudaFuncAttributeMaxDynamicSharedMemorySize, dynA);
    cudaFuncSetAttribute(k_oproj2,  cudaFuncAttributeMaxDynamicSharedMemorySize, dynO2);

    const int PREP_N = ND * NH + NH * ND + NH * NH + 3 * NH * NH + 384;
    k_prep<<<(PREP_N + 255) / 256, 256>>>(W1, W2, Wo, Wq, Wk, Wv, bq, bk, bv);

    k1_mma<<<GM1, 256, dynG1>>>(x, b1, ln_g, ln_b);
    k_gateqkv<<<NB / 4, 256, dynQ>>>(T_W, T_b, n_g, n_b);
    k_att<<<NB, 256, dynA>>>();
    k_oproj2<<<GM1, 256, dynO2>>>(bo, b2, out);
}